// round 1
// baseline (speedup 1.0000x reference)
#include <cuda_runtime.h>
#include <math.h>

#define BATCH 4
#define SEQ   1024
#define DIM   1024
#define HEADS 16
#define HD    64
#define MLPD  4096
#define DEPTH 4
#define MROWS (BATCH*SEQ)          // 4096
#define ATT_SCALE (1.0f/32.0f)     // DIM^-0.5

// ------------------- scratch (no allocation allowed) -------------------
__device__ float g_h   [MROWS*DIM];     // 16 MB
__device__ float g_qkv [MROWS*3*DIM];   // 48 MB
__device__ float g_o   [MROWS*DIM];     // 16 MB
__device__ float g_mlp [MROWS*MLPD];    // 64 MB

// ------------------- LayerNorm -------------------
__global__ void ln_kernel(const float* __restrict__ x, const float* __restrict__ g,
                          const float* __restrict__ b, float* __restrict__ out) {
    int row = blockIdx.x;
    const float* xr = x + (size_t)row * DIM;
    int t = threadIdx.x;
    float v[4];
    float s = 0.f, s2 = 0.f;
#pragma unroll
    for (int i = 0; i < 4; i++) {
        float u = xr[t + i * 256];
        v[i] = u; s += u; s2 += u * u;
    }
    __shared__ float red[17];
#pragma unroll
    for (int o = 16; o > 0; o >>= 1) {
        s  += __shfl_xor_sync(0xffffffffu, s,  o);
        s2 += __shfl_xor_sync(0xffffffffu, s2, o);
    }
    int w = t >> 5;
    if ((t & 31) == 0) { red[w] = s; red[w + 8] = s2; }
    __syncthreads();
    if (t < 32) {
        s  = (t < 8) ? red[t]     : 0.f;
        s2 = (t < 8) ? red[t + 8] : 0.f;
#pragma unroll
        for (int o = 4; o > 0; o >>= 1) {
            s  += __shfl_xor_sync(0xffffffffu, s,  o);
            s2 += __shfl_xor_sync(0xffffffffu, s2, o);
        }
        if (t == 0) {
            float mean = s * (1.0f / DIM);
            float var  = s2 * (1.0f / DIM) - mean * mean;
            red[0]  = mean;
            red[16] = rsqrtf(var + 1e-5f);
        }
    }
    __syncthreads();
    float mean = red[0], rstd = red[16];
    float* orow = out + (size_t)row * DIM;
#pragma unroll
    for (int i = 0; i < 4; i++) {
        int c = t + i * 256;
        orow[c] = (v[i] - mean) * rstd * g[c] + b[c];
    }
}

// ------------------- SGEMM 128x128x8, 8x8 microtile -------------------
// EPI: 0 = plain, 2 = bias+gelu, 3 = bias+residual
template<int EPI>
__global__ __launch_bounds__(256)
void sgemm(const float* __restrict__ A, const float* __restrict__ Bm,
           const float* __restrict__ bias, const float* __restrict__ res,
           float* __restrict__ C, int K, int Ndim) {
    __shared__ float As[8 * 128];   // transposed: As[k][m]
    __shared__ float Bs[8 * 128];   // Bs[k][n]
    int tid = threadIdx.x;
    int tx = tid & 15, ty = tid >> 4;
    int brow = blockIdx.y << 7;
    int bcol = blockIdx.x << 7;

    int arow = tid >> 1;            // 0..127
    int acol = (tid & 1) << 2;      // 0 or 4
    int bwr  = tid >> 5;            // 0..7
    int bwc  = (tid & 31) << 2;     // 0..124

    const float* Aptr = A + (size_t)(brow + arow) * K + acol;
    const float* Bptr = Bm + (size_t)bwr * Ndim + bcol + bwc;

    float acc[8][8];
#pragma unroll
    for (int i = 0; i < 8; i++)
#pragma unroll
        for (int j = 0; j < 8; j++) acc[i][j] = 0.f;

    for (int kt = 0; kt < K; kt += 8) {
        float4 av = *(const float4*)(Aptr + kt);
        float4 bv = *(const float4*)(Bptr + (size_t)kt * Ndim);
        As[(acol + 0) * 128 + arow] = av.x;
        As[(acol + 1) * 128 + arow] = av.y;
        As[(acol + 2) * 128 + arow] = av.z;
        As[(acol + 3) * 128 + arow] = av.w;
        *(float4*)&Bs[bwr * 128 + bwc] = bv;
        __syncthreads();
#pragma unroll
        for (int k = 0; k < 8; k++) {
            float a[8], bb[8];
            *(float4*)&a[0]  = *(const float4*)&As[k * 128 + (ty << 2)];
            *(float4*)&a[4]  = *(const float4*)&As[k * 128 + 64 + (ty << 2)];
            *(float4*)&bb[0] = *(const float4*)&Bs[k * 128 + (tx << 2)];
            *(float4*)&bb[4] = *(const float4*)&Bs[k * 128 + 64 + (tx << 2)];
#pragma unroll
            for (int i = 0; i < 8; i++)
#pragma unroll
                for (int j = 0; j < 8; j++)
                    acc[i][j] = fmaf(a[i], bb[j], acc[i][j]);
        }
        __syncthreads();
    }

#pragma unroll
    for (int i = 0; i < 8; i++) {
        int row = brow + ((i < 4) ? ((ty << 2) + i) : (64 + (ty << 2) + i - 4));
#pragma unroll
        for (int jh = 0; jh < 2; jh++) {
            int col = bcol + ((jh == 0) ? (tx << 2) : (64 + (tx << 2)));
            float4 v;
            float* pv = &v.x;
#pragma unroll
            for (int j = 0; j < 4; j++) {
                float u = acc[i][jh * 4 + j];
                if (EPI >= 2) u += bias[col + j];
                if (EPI == 2) u = 0.5f * u * (1.0f + erff(u * 0.70710678118654752f));
                if (EPI == 3) u += res[(size_t)row * Ndim + col + j];
                pv[j] = u;
            }
            *(float4*)&C[(size_t)row * Ndim + col] = v;
        }
    }
}

// ------------------- Flash attention (64-row query tile, full head_dim=64) -------------------
#define APAD 68
#define ATT_SMEM (4 * 64 * APAD * 4)   // Qt, Kt, Vs, Ps  = 69632 bytes

__global__ __launch_bounds__(256)
void attn_kernel(const float* __restrict__ qkv, float* __restrict__ o) {
    extern __shared__ float sm[];
    float* Qt = sm;                    // [d][r]  64 x 68
    float* Kt = sm + 64 * APAD;        // [d][c]
    float* Vs = sm + 2 * 64 * APAD;    // [k][c]
    float* Ps = sm + 3 * 64 * APAD;    // [r][k]

    int bh = blockIdx.y;
    int b = bh >> 4, h = bh & 15;
    int q0 = blockIdx.x << 6;
    const float* gq = qkv + (size_t)b * SEQ * 3 * DIM + h * HD;
    const float* gk = gq + DIM;
    const float* gv = gq + 2 * DIM;

    int t = threadIdx.x;
    int tx = t & 15, ty = t >> 4;

    for (int e = t; e < 4096; e += 256) {
        int r = e >> 6, d = e & 63;
        Qt[d * APAD + r] = gq[(size_t)(q0 + r) * (3 * DIM) + d];
    }

    float m[4], l[4], acc[4][4];
#pragma unroll
    for (int i = 0; i < 4; i++) {
        m[i] = -1e30f; l[i] = 0.f;
#pragma unroll
        for (int j = 0; j < 4; j++) acc[i][j] = 0.f;
    }

    for (int kt = 0; kt < SEQ; kt += 64) {
        __syncthreads();
        for (int e = t; e < 4096; e += 256) {
            int r = e >> 6, d = e & 63;
            Kt[d * APAD + r] = gk[(size_t)(kt + r) * (3 * DIM) + d];
            Vs[r * APAD + d] = gv[(size_t)(kt + r) * (3 * DIM) + d];
        }
        __syncthreads();

        float s[4][4];
#pragma unroll
        for (int i = 0; i < 4; i++)
#pragma unroll
            for (int j = 0; j < 4; j++) s[i][j] = 0.f;

#pragma unroll 8
        for (int d = 0; d < 64; d++) {
            float4 qv = *(const float4*)&Qt[d * APAD + (ty << 2)];
            float4 kv = *(const float4*)&Kt[d * APAD + (tx << 2)];
            float qa[4] = {qv.x, qv.y, qv.z, qv.w};
            float ka[4] = {kv.x, kv.y, kv.z, kv.w};
#pragma unroll
            for (int i = 0; i < 4; i++)
#pragma unroll
                for (int j = 0; j < 4; j++)
                    s[i][j] = fmaf(qa[i], ka[j], s[i][j]);
        }

#pragma unroll
        for (int i = 0; i < 4; i++) {
            float s0 = s[i][0] * ATT_SCALE, s1 = s[i][1] * ATT_SCALE;
            float s2 = s[i][2] * ATT_SCALE, s3 = s[i][3] * ATT_SCALE;
            float mx = fmaxf(fmaxf(s0, s1), fmaxf(s2, s3));
#pragma unroll
            for (int off = 8; off > 0; off >>= 1)
                mx = fmaxf(mx, __shfl_xor_sync(0xffffffffu, mx, off));
            float nm = fmaxf(m[i], mx);
            float corr = __expf(m[i] - nm);
            float p0 = __expf(s0 - nm), p1 = __expf(s1 - nm);
            float p2 = __expf(s2 - nm), p3 = __expf(s3 - nm);
            float ls = p0 + p1 + p2 + p3;
#pragma unroll
            for (int off = 8; off > 0; off >>= 1)
                ls += __shfl_xor_sync(0xffffffffu, ls, off);
            l[i] = l[i] * corr + ls;
            m[i] = nm;
#pragma unroll
            for (int j = 0; j < 4; j++) acc[i][j] *= corr;
            float4 pv = make_float4(p0, p1, p2, p3);
            *(float4*)&Ps[((ty << 2) + i) * APAD + (tx << 2)] = pv;
        }
        __syncthreads();

#pragma unroll 4
        for (int k = 0; k < 64; k++) {
            float4 vv = *(const float4*)&Vs[k * APAD + (tx << 2)];
#pragma unroll
            for (int i = 0; i < 4; i++) {
                float p = Ps[((ty << 2) + i) * APAD + k];
                acc[i][0] = fmaf(p, vv.x, acc[i][0]);
                acc[i][1] = fmaf(p, vv.y, acc[i][1]);
                acc[i][2] = fmaf(p, vv.z, acc[i][2]);
                acc[i][3] = fmaf(p, vv.w, acc[i][3]);
            }
        }
    }

#pragma unroll
    for (int i = 0; i < 4; i++) {
        float inv = 1.0f / l[i];
        int r = q0 + (ty << 2) + i;
        float4 ov = make_float4(acc[i][0] * inv, acc[i][1] * inv,
                                acc[i][2] * inv, acc[i][3] * inv);
        *(float4*)&o[(size_t)b * SEQ * DIM + (size_t)r * DIM + h * HD + (tx << 2)] = ov;
    }
}

// ------------------- host orchestration -------------------
extern "C" void kernel_launch(void* const* d_in, const int* in_sizes, int n_in,
                              void* d_out, int out_size) {
    const float* x     = (const float*)d_in[0];
    const float* ln1_g = (const float*)d_in[1];
    const float* ln1_b = (const float*)d_in[2];
    const float* w_qkv = (const float*)d_in[3];
    const float* w_out = (const float*)d_in[4];
    const float* b_out = (const float*)d_in[5];
    const float* ln2_g = (const float*)d_in[6];
    const float* ln2_b = (const float*)d_in[7];
    const float* w1    = (const float*)d_in[8];
    const float* b1    = (const float*)d_in[9];
    const float* w2    = (const float*)d_in[10];
    const float* b2    = (const float*)d_in[11];
    float* out = (float*)d_out;

    float *h, *qkvb, *ob, *mlpb;
    cudaGetSymbolAddress((void**)&h,    g_h);
    cudaGetSymbolAddress((void**)&qkvb, g_qkv);
    cudaGetSymbolAddress((void**)&ob,   g_o);
    cudaGetSymbolAddress((void**)&mlpb, g_mlp);

    cudaFuncSetAttribute(attn_kernel, cudaFuncAttributeMaxDynamicSharedMemorySize, ATT_SMEM);

    cudaMemcpyAsync(out, x, (size_t)MROWS * DIM * sizeof(float),
                    cudaMemcpyDeviceToDevice);

    for (int lyr = 0; lyr < DEPTH; lyr++) {
        // --- attention block ---
        ln_kernel<<<MROWS, 256>>>(out, ln1_g + lyr * DIM, ln1_b + lyr * DIM, h);
        sgemm<0><<<dim3(3 * DIM / 128, MROWS / 128), 256>>>(
            h, w_qkv + (size_t)lyr * DIM * 3 * DIM, nullptr, nullptr,
            qkvb, DIM, 3 * DIM);
        attn_kernel<<<dim3(SEQ / 64, BATCH * HEADS), 256, ATT_SMEM>>>(qkvb, ob);
        sgemm<3><<<dim3(DIM / 128, MROWS / 128), 256>>>(
            ob, w_out + (size_t)lyr * DIM * DIM, b_out + lyr * DIM, out,
            out, DIM, DIM);
        // --- MLP block ---
        ln_kernel<<<MROWS, 256>>>(out, ln2_g + lyr * DIM, ln2_b + lyr * DIM, h);
        sgemm<2><<<dim3(MLPD / 128, MROWS / 128), 256>>>(
            h, w1 + (size_t)lyr * DIM * MLPD, b1 + (size_t)lyr * MLPD, nullptr,
            mlpb, DIM, MLPD);
        sgemm<3><<<dim3(DIM / 128, MROWS / 128), 256>>>(
            mlpb, w2 + (size_t)lyr * MLPD * DIM, b2 + lyr * DIM, out,
            out, MLPD, DIM);
    }
}

// round 3
// speedup vs baseline: 2.7446x; 2.7446x over previous
#include <cuda_runtime.h>
#include <math.h>
#include <stdint.h>

#define BATCH 4
#define SEQ   1024
#define DIM   1024
#define HEADS 16
#define HD    64
#define MLPD  4096
#define DEPTH 4
#define MROWS (BATCH*SEQ)          // 4096
#define ATT_SCALE (1.0f/32.0f)     // DIM^-0.5

// ------------------- scratch (no allocation allowed) -------------------
__device__ float g_h   [MROWS*DIM];
__device__ float g_qkv [MROWS*3*DIM];
__device__ float g_o   [MROWS*DIM];
__device__ float g_mlp [MROWS*MLPD];
// transposed (N-major) tf32-rounded weights
__device__ float g_wt_qkv[DEPTH*3*DIM*DIM];
__device__ float g_wt_out[DEPTH*DIM*DIM];
__device__ float g_wt1   [DEPTH*MLPD*DIM];
__device__ float g_wt2   [DEPTH*DIM*MLPD];

// ------------------- helpers -------------------
__device__ __forceinline__ uint32_t smem_u32(const void* p) {
    uint32_t a;
    asm("{ .reg .u64 t; cvta.to.shared.u64 t, %1; cvt.u32.u64 %0, t; }" : "=r"(a) : "l"(p));
    return a;
}
__device__ __forceinline__ float rna_tf32(float x) {
    float r; asm("cvt.rna.tf32.f32 %0, %1;" : "=f"(r) : "f"(x)); return r;
}
static __device__ __forceinline__ uint32_t sw128(uint32_t off) {
    return off ^ ((off >> 3) & 0x70);
}
__device__ __forceinline__ void ldsm4(uint32_t& d0, uint32_t& d1, uint32_t& d2,
                                      uint32_t& d3, uint32_t addr) {
    asm volatile("ldmatrix.sync.aligned.m8n8.x4.shared.b16 {%0,%1,%2,%3}, [%4];"
                 : "=r"(d0), "=r"(d1), "=r"(d2), "=r"(d3) : "r"(addr));
}
__device__ __forceinline__ void mma_tf32(float* c, const uint32_t* a,
                                         uint32_t b0, uint32_t b1) {
    asm volatile(
        "mma.sync.aligned.m16n8k8.row.col.f32.tf32.tf32.f32 "
        "{%0,%1,%2,%3}, {%4,%5,%6,%7}, {%8,%9}, {%0,%1,%2,%3};"
        : "+f"(c[0]), "+f"(c[1]), "+f"(c[2]), "+f"(c[3])
        : "r"(a[0]), "r"(a[1]), "r"(a[2]), "r"(a[3]), "r"(b0), "r"(b1));
}
__device__ __forceinline__ void cp_async16(uint32_t dst, const void* src) {
    asm volatile("cp.async.ca.shared.global [%0], [%1], 16;"
                 :: "r"(dst), "l"(src) : "memory");
}
#define CP_COMMIT() asm volatile("cp.async.commit_group;" ::: "memory")
#define CP_WAIT(n)  asm volatile("cp.async.wait_group %0;" :: "n"(n) : "memory")

// ------------------- LayerNorm -------------------
__global__ void ln_kernel(const float* __restrict__ x, const float* __restrict__ g,
                          const float* __restrict__ b, float* __restrict__ out) {
    int row = blockIdx.x;
    const float* xr = x + (size_t)row * DIM;
    int t = threadIdx.x;
    float v[4];
    float s = 0.f, s2 = 0.f;
#pragma unroll
    for (int i = 0; i < 4; i++) {
        float u = xr[t + i * 256];
        v[i] = u; s += u; s2 += u * u;
    }
    __shared__ float red[17];
#pragma unroll
    for (int o = 16; o > 0; o >>= 1) {
        s  += __shfl_xor_sync(0xffffffffu, s,  o);
        s2 += __shfl_xor_sync(0xffffffffu, s2, o);
    }
    int w = t >> 5;
    if ((t & 31) == 0) { red[w] = s; red[w + 8] = s2; }
    __syncthreads();
    if (t < 32) {
        s  = (t < 8) ? red[t]     : 0.f;
        s2 = (t < 8) ? red[t + 8] : 0.f;
#pragma unroll
        for (int o = 4; o > 0; o >>= 1) {
            s  += __shfl_xor_sync(0xffffffffu, s,  o);
            s2 += __shfl_xor_sync(0xffffffffu, s2, o);
        }
        if (t == 0) {
            float mean = s * (1.0f / DIM);
            float var  = s2 * (1.0f / DIM) - mean * mean;
            red[0]  = mean;
            red[16] = rsqrtf(var + 1e-5f);
        }
    }
    __syncthreads();
    float mean = red[0], rstd = red[16];
    float* orow = out + (size_t)row * DIM;
#pragma unroll
    for (int i = 0; i < 4; i++) {
        int c = t + i * 256;
        orow[c] = (v[i] - mean) * rstd * g[c] + b[c];
    }
}

// ------------------- weight transpose + tf32 round: Wt[n][k] = rna(W[k][n]) ----
__global__ void transpose_rna(const float* __restrict__ W, float* __restrict__ Wt,
                              int K, int N) {
    __shared__ float t[32][33];
    int bx = blockIdx.x * 32, by = blockIdx.y * 32;
    int x = threadIdx.x, y = threadIdx.y;
#pragma unroll
    for (int i = 0; i < 32; i += 8)
        t[y + i][x] = W[(size_t)(by + y + i) * N + bx + x];
    __syncthreads();
#pragma unroll
    for (int i = 0; i < 32; i += 8)
        Wt[(size_t)(bx + y + i) * K + by + x] = rna_tf32(t[x][y + i]);
}

// ------------------- mma.sync tf32 GEMM: C[M,N] = A[M,K] * Bt[N,K]^T ---------
// CTA tile 128x128, BK=32, double-buffered smem, 8 warps (2m x 4n), warp 64x32
#define GM_BUF 16384
#define GM_SMEM (4 * GM_BUF + 1024)

template<int EPI>  // 0 plain, 2 bias+gelu, 3 bias+residual
__global__ __launch_bounds__(256)
void gemm_mma(const float* __restrict__ A, const float* __restrict__ Bt,
              const float* __restrict__ bias, const float* __restrict__ res,
              float* __restrict__ C, int K, int Ndim) {
    extern __shared__ char smraw[];
    uint32_t sbase = (smem_u32(smraw) + 1023u) & ~1023u;

    int tid = threadIdx.x;
    int wid = tid >> 5, lane = tid & 31;
    int wm = wid & 1, wn = wid >> 1;
    int brow = blockIdx.y << 7, bcol = blockIdx.x << 7;
    int g = lane >> 3, r = lane & 7;

    float acc[4][4][4];
#pragma unroll
    for (int i = 0; i < 4; i++)
#pragma unroll
        for (int j = 0; j < 4; j++)
#pragma unroll
            for (int q = 0; q < 4; q++) acc[i][j][q] = 0.f;

    const int KT = K >> 5;
    int arow = tid >> 1;                 // A: 2 chunks/thread per half? no:
    // A tile: 128 rows x 8 chunks = 1024 chunks; idx = tid + i*256
    // B tile same count via cp.async
    float4 aprefetch[4];

    // ---- prologue: A(0) LDG, B(0) cp.async ----
    {
        const float* Ab = A + (size_t)brow * K;
#pragma unroll
        for (int i = 0; i < 4; i++) {
            int idx = tid + i * 256;
            int rr = idx >> 3, ck = idx & 7;
            aprefetch[i] = *(const float4*)(Ab + (size_t)rr * K + (ck << 2));
        }
        const float* Bb = Bt + (size_t)bcol * K;
#pragma unroll
        for (int i = 0; i < 4; i++) {
            int idx = tid + i * 256;
            int rr = idx >> 3, ck = idx & 7;
            uint32_t dst = sbase + 2 * GM_BUF + sw128((uint32_t)(rr * 128 + (ck << 4)));
            cp_async16(dst, Bb + (size_t)rr * K + (ck << 2));
        }
        CP_COMMIT();
    }

    for (int kt = 0; kt < KT; kt++) {
        int b = kt & 1;
        uint32_t Ab_s = sbase + b * GM_BUF;
        uint32_t Bb_s = sbase + 2 * GM_BUF + b * GM_BUF;
        // STS A(kt) from regs (rounded)
#pragma unroll
        for (int i = 0; i < 4; i++) {
            int idx = tid + i * 256;
            int rr = idx >> 3, ck = idx & 7;
            float4 v = aprefetch[i];
            v.x = rna_tf32(v.x); v.y = rna_tf32(v.y);
            v.z = rna_tf32(v.z); v.w = rna_tf32(v.w);
            *(float4*)(smraw + (Ab_s - smem_u32(smraw)) + sw128((uint32_t)(rr * 128 + (ck << 4)))) = v;
        }
        // prefetch kt+1
        if (kt + 1 < KT) {
            const float* Ab = A + (size_t)brow * K + ((kt + 1) << 5);
#pragma unroll
            for (int i = 0; i < 4; i++) {
                int idx = tid + i * 256;
                int rr = idx >> 3, ck = idx & 7;
                aprefetch[i] = *(const float4*)(Ab + (size_t)rr * K + (ck << 2));
            }
            const float* Bb = Bt + (size_t)bcol * K + ((kt + 1) << 5);
            uint32_t Bnext = sbase + 2 * GM_BUF + (b ^ 1) * GM_BUF;
#pragma unroll
            for (int i = 0; i < 4; i++) {
                int idx = tid + i * 256;
                int rr = idx >> 3, ck = idx & 7;
                cp_async16(Bnext + sw128((uint32_t)(rr * 128 + (ck << 4))),
                           Bb + (size_t)rr * K + (ck << 2));
            }
            CP_COMMIT();
            CP_WAIT(1);
        } else {
            CP_WAIT(0);
        }
        __syncthreads();

        // ---- compute on buffer b ----
#pragma unroll
        for (int ks = 0; ks < 4; ks++) {
            uint32_t afr[4][4];
#pragma unroll
            for (int im = 0; im < 4; im++) {
                int rowa = wm * 64 + im * 16 + r + (g & 1) * 8;
                uint32_t ck = (uint32_t)(ks * 2 + (g >> 1));
                ldsm4(afr[im][0], afr[im][1], afr[im][2], afr[im][3],
                      Ab_s + sw128((uint32_t)(rowa * 128) + (ck << 4)));
            }
            uint32_t bfr[4][2];
#pragma unroll
            for (int ip = 0; ip < 2; ip++) {
                int rowb = wn * 32 + ip * 16 + (g >> 1) * 8 + r;
                uint32_t ck = (uint32_t)(ks * 2 + (g & 1));
                ldsm4(bfr[2 * ip][0], bfr[2 * ip][1], bfr[2 * ip + 1][0], bfr[2 * ip + 1][1],
                      Bb_s + sw128((uint32_t)(rowb * 128) + (ck << 4)));
            }
#pragma unroll
            for (int im = 0; im < 4; im++)
#pragma unroll
                for (int in = 0; in < 4; in++)
                    mma_tf32(acc[im][in], afr[im], bfr[in][0], bfr[in][1]);
        }
        // barrier before next iter's STS overwrites (handled by top-of-loop sync)
        if (kt + 1 < KT) __syncthreads();
    }

    // ---- epilogue ----
    int lr = lane >> 2, lc = (lane & 3) << 1;
#pragma unroll
    for (int im = 0; im < 4; im++) {
#pragma unroll
        for (int half = 0; half < 2; half++) {
            int row = brow + wm * 64 + im * 16 + lr + half * 8;
            float* Crow = C + (size_t)row * Ndim;
            const float* Rrow = (EPI == 3) ? (res + (size_t)row * Ndim) : nullptr;
#pragma unroll
            for (int in = 0; in < 4; in++) {
                int col = bcol + wn * 32 + in * 8 + lc;
                float u0 = acc[im][in][half * 2 + 0];
                float u1 = acc[im][in][half * 2 + 1];
                if (EPI >= 2) { u0 += bias[col]; u1 += bias[col + 1]; }
                if (EPI == 2) {
                    u0 = 0.5f * u0 * (1.0f + erff(u0 * 0.70710678118654752f));
                    u1 = 0.5f * u1 * (1.0f + erff(u1 * 0.70710678118654752f));
                }
                if (EPI == 3) { u0 += Rrow[col]; u1 += Rrow[col + 1]; }
                float2 v = make_float2(u0, u1);
                *(float2*)(Crow + col) = v;
            }
        }
    }
}

// ------------------- Flash attention (fp32 SIMT) -------------------
#define APAD 68
#define ATT_SMEM (4 * 64 * APAD * 4)

__global__ __launch_bounds__(256)
void attn_kernel(const float* __restrict__ qkv, float* __restrict__ o) {
    extern __shared__ float smf[];
    float* Qt = smf;
    float* Kt = smf + 64 * APAD;
    float* Vs = smf + 2 * 64 * APAD;
    float* Ps = smf + 3 * 64 * APAD;

    int bh = blockIdx.y;
    int b = bh >> 4, h = bh & 15;
    int q0 = blockIdx.x << 6;
    const float* gq = qkv + (size_t)b * SEQ * 3 * DIM + h * HD;
    const float* gk = gq + DIM;
    const float* gv = gq + 2 * DIM;

    int t = threadIdx.x;
    int tx = t & 15, ty = t >> 4;

    for (int e = t; e < 4096; e += 256) {
        int rr = e >> 6, d = e & 63;
        Qt[d * APAD + rr] = gq[(size_t)(q0 + rr) * (3 * DIM) + d];
    }

    float m[4], l[4], acc[4][4];
#pragma unroll
    for (int i = 0; i < 4; i++) {
        m[i] = -1e30f; l[i] = 0.f;
#pragma unroll
        for (int j = 0; j < 4; j++) acc[i][j] = 0.f;
    }

    for (int kt = 0; kt < SEQ; kt += 64) {
        __syncthreads();
        for (int e = t; e < 4096; e += 256) {
            int rr = e >> 6, d = e & 63;
            Kt[d * APAD + rr] = gk[(size_t)(kt + rr) * (3 * DIM) + d];
            Vs[rr * APAD + d] = gv[(size_t)(kt + rr) * (3 * DIM) + d];
        }
        __syncthreads();

        float s[4][4];
#pragma unroll
        for (int i = 0; i < 4; i++)
#pragma unroll
            for (int j = 0; j < 4; j++) s[i][j] = 0.f;

#pragma unroll 8
        for (int d = 0; d < 64; d++) {
            float4 qv = *(const float4*)&Qt[d * APAD + (ty << 2)];
            float4 kv = *(const float4*)&Kt[d * APAD + (tx << 2)];
            float qa[4] = {qv.x, qv.y, qv.z, qv.w};
            float ka[4] = {kv.x, kv.y, kv.z, kv.w};
#pragma unroll
            for (int i = 0; i < 4; i++)
#pragma unroll
                for (int j = 0; j < 4; j++)
                    s[i][j] = fmaf(qa[i], ka[j], s[i][j]);
        }

#pragma unroll
        for (int i = 0; i < 4; i++) {
            float s0 = s[i][0] * ATT_SCALE, s1 = s[i][1] * ATT_SCALE;
            float s2 = s[i][2] * ATT_SCALE, s3 = s[i][3] * ATT_SCALE;
            float mx = fmaxf(fmaxf(s0, s1), fmaxf(s2, s3));
#pragma unroll
            for (int off = 8; off > 0; off >>= 1)
                mx = fmaxf(mx, __shfl_xor_sync(0xffffffffu, mx, off));
            float nm = fmaxf(m[i], mx);
            float corr = __expf(m[i] - nm);
            float p0 = __expf(s0 - nm), p1 = __expf(s1 - nm);
            float p2 = __expf(s2 - nm), p3 = __expf(s3 - nm);
            float ls = p0 + p1 + p2 + p3;
#pragma unroll
            for (int off = 8; off > 0; off >>= 1)
                ls += __shfl_xor_sync(0xffffffffu, ls, off);
            l[i] = l[i] * corr + ls;
            m[i] = nm;
#pragma unroll
            for (int j = 0; j < 4; j++) acc[i][j] *= corr;
            float4 pv = make_float4(p0, p1, p2, p3);
            *(float4*)&Ps[((ty << 2) + i) * APAD + (tx << 2)] = pv;
        }
        __syncthreads();

#pragma unroll 4
        for (int k = 0; k < 64; k++) {
            float4 vv = *(const float4*)&Vs[k * APAD + (tx << 2)];
#pragma unroll
            for (int i = 0; i < 4; i++) {
                float p = Ps[((ty << 2) + i) * APAD + k];
                acc[i][0] = fmaf(p, vv.x, acc[i][0]);
                acc[i][1] = fmaf(p, vv.y, acc[i][1]);
                acc[i][2] = fmaf(p, vv.z, acc[i][2]);
                acc[i][3] = fmaf(p, vv.w, acc[i][3]);
            }
        }
    }

#pragma unroll
    for (int i = 0; i < 4; i++) {
        float inv = 1.0f / l[i];
        int rr = q0 + (ty << 2) + i;
        float4 ov = make_float4(acc[i][0] * inv, acc[i][1] * inv,
                                acc[i][2] * inv, acc[i][3] * inv);
        *(float4*)&o[(size_t)b * SEQ * DIM + (size_t)rr * DIM + h * HD + (tx << 2)] = ov;
    }
}

// ------------------- host orchestration -------------------
extern "C" void kernel_launch(void* const* d_in, const int* in_sizes, int n_in,
                              void* d_out, int out_size) {
    const float* x     = (const float*)d_in[0];
    const float* ln1_g = (const float*)d_in[1];
    const float* ln1_b = (const float*)d_in[2];
    const float* w_qkv = (const float*)d_in[3];
    const float* w_out = (const float*)d_in[4];
    const float* b_out = (const float*)d_in[5];
    const float* ln2_g = (const float*)d_in[6];
    const float* ln2_b = (const float*)d_in[7];
    const float* w1    = (const float*)d_in[8];
    const float* b1    = (const float*)d_in[9];
    const float* w2    = (const float*)d_in[10];
    const float* b2    = (const float*)d_in[11];
    float* out = (float*)d_out;

    float *h, *qkvb, *ob, *mlpb, *wtq, *wto, *wt1, *wt2;
    cudaGetSymbolAddress((void**)&h,    g_h);
    cudaGetSymbolAddress((void**)&qkvb, g_qkv);
    cudaGetSymbolAddress((void**)&ob,   g_o);
    cudaGetSymbolAddress((void**)&mlpb, g_mlp);
    cudaGetSymbolAddress((void**)&wtq,  g_wt_qkv);
    cudaGetSymbolAddress((void**)&wto,  g_wt_out);
    cudaGetSymbolAddress((void**)&wt1,  g_wt1);
    cudaGetSymbolAddress((void**)&wt2,  g_wt2);

    cudaFuncSetAttribute(attn_kernel, cudaFuncAttributeMaxDynamicSharedMemorySize, ATT_SMEM);
    cudaFuncSetAttribute(gemm_mma<0>, cudaFuncAttributeMaxDynamicSharedMemorySize, GM_SMEM);
    cudaFuncSetAttribute(gemm_mma<2>, cudaFuncAttributeMaxDynamicSharedMemorySize, GM_SMEM);
    cudaFuncSetAttribute(gemm_mma<3>, cudaFuncAttributeMaxDynamicSharedMemorySize, GM_SMEM);

    // pre-transpose + tf32-round all weights
    dim3 tb(32, 8);
    for (int l = 0; l < DEPTH; l++) {
        transpose_rna<<<dim3(3 * DIM / 32, DIM / 32), tb>>>(
            w_qkv + (size_t)l * DIM * 3 * DIM, wtq + (size_t)l * 3 * DIM * DIM, DIM, 3 * DIM);
        transpose_rna<<<dim3(DIM / 32, DIM / 32), tb>>>(
            w_out + (size_t)l * DIM * DIM, wto + (size_t)l * DIM * DIM, DIM, DIM);
        transpose_rna<<<dim3(MLPD / 32, DIM / 32), tb>>>(
            w1 + (size_t)l * DIM * MLPD, wt1 + (size_t)l * MLPD * DIM, DIM, MLPD);
        transpose_rna<<<dim3(DIM / 32, MLPD / 32), tb>>>(
            w2 + (size_t)l * MLPD * DIM, wt2 + (size_t)l * DIM * MLPD, MLPD, DIM);
    }

    cudaMemcpyAsync(out, x, (size_t)MROWS * DIM * sizeof(float),
                    cudaMemcpyDeviceToDevice);

    for (int lyr = 0; lyr < DEPTH; lyr++) {
        // --- attention block ---
        ln_kernel<<<MROWS, 256>>>(out, ln1_g + lyr * DIM, ln1_b + lyr * DIM, h);
        gemm_mma<0><<<dim3(3 * DIM / 128, MROWS / 128), 256, GM_SMEM>>>(
            h, wtq + (size_t)lyr * 3 * DIM * DIM, nullptr, nullptr,
            qkvb, DIM, 3 * DIM);
        attn_kernel<<<dim3(SEQ / 64, BATCH * HEADS), 256, ATT_SMEM>>>(qkvb, ob);
        gemm_mma<3><<<dim3(DIM / 128, MROWS / 128), 256, GM_SMEM>>>(
            ob, wto + (size_t)lyr * DIM * DIM, b_out + lyr * DIM, out,
            out, DIM, DIM);
        // --- MLP block ---
        ln_kernel<<<MROWS, 256>>>(out, ln2_g + lyr * DIM, ln2_b + lyr * DIM, h);
        gemm_mma<2><<<dim3(MLPD / 128, MROWS / 128), 256, GM_SMEM>>>(
            h, wt1 + (size_t)lyr * MLPD * DIM, b1 + (size_t)lyr * MLPD, nullptr,
            mlpb, DIM, MLPD);
        gemm_mma<3><<<dim3(DIM / 128, MROWS / 128), 256, GM_SMEM>>>(
            mlpb, wt2 + (size_t)lyr * DIM * MLPD, b2 + lyr * DIM, out,
            out, MLPD, DIM);
    }
}

// round 5
// speedup vs baseline: 3.7238x; 1.3568x over previous
#include <cuda_runtime.h>
#include <math.h>
#include <stdint.h>

#define BATCH 4
#define SEQ   1024
#define DIM   1024
#define HEADS 16
#define HD    64
#define MLPD  4096
#define DEPTH 4
#define MROWS (BATCH*SEQ)          // 4096
#define ATT_SCALE (1.0f/32.0f)     // DIM^-0.5

// ------------------- scratch (no allocation allowed) -------------------
__device__ float g_h   [MROWS*DIM];
__device__ float g_qkv [MROWS*3*DIM];
__device__ float g_o   [MROWS*DIM];
__device__ float g_mlp [MROWS*MLPD];
// transposed (N-major) tf32-rounded weights
__device__ float g_wt_qkv[DEPTH*3*DIM*DIM];
__device__ float g_wt_out[DEPTH*DIM*DIM];
__device__ float g_wt1   [DEPTH*MLPD*DIM];
__device__ float g_wt2   [DEPTH*DIM*MLPD];

// ------------------- helpers -------------------
__device__ __forceinline__ uint32_t smem_u32(const void* p) {
    uint32_t a;
    asm("{ .reg .u64 t; cvta.to.shared.u64 t, %1; cvt.u32.u64 %0, t; }" : "=r"(a) : "l"(p));
    return a;
}
__device__ __forceinline__ float rna_tf32(float x) {
    float r; asm("cvt.rna.tf32.f32 %0, %1;" : "=f"(r) : "f"(x)); return r;
}
static __device__ __forceinline__ uint32_t sw128(uint32_t off) {
    return off ^ ((off >> 3) & 0x70);
}
__device__ __forceinline__ void ldsm4(uint32_t& d0, uint32_t& d1, uint32_t& d2,
                                      uint32_t& d3, uint32_t addr) {
    asm volatile("ldmatrix.sync.aligned.m8n8.x4.shared.b16 {%0,%1,%2,%3}, [%4];"
                 : "=r"(d0), "=r"(d1), "=r"(d2), "=r"(d3) : "r"(addr));
}
__device__ __forceinline__ void mma_tf32(float* c, const uint32_t* a,
                                         uint32_t b0, uint32_t b1) {
    asm volatile(
        "mma.sync.aligned.m16n8k8.row.col.f32.tf32.tf32.f32 "
        "{%0,%1,%2,%3}, {%4,%5,%6,%7}, {%8,%9}, {%0,%1,%2,%3};"
        : "+f"(c[0]), "+f"(c[1]), "+f"(c[2]), "+f"(c[3])
        : "r"(a[0]), "r"(a[1]), "r"(a[2]), "r"(a[3]), "r"(b0), "r"(b1));
}
__device__ __forceinline__ void cp_async16(uint32_t dst, const void* src) {
    asm volatile("cp.async.ca.shared.global [%0], [%1], 16;"
                 :: "r"(dst), "l"(src) : "memory");
}
#define CP_COMMIT() asm volatile("cp.async.commit_group;" ::: "memory")
#define CP_WAIT(n)  asm volatile("cp.async.wait_group %0;" :: "n"(n) : "memory")

// ------------------- LayerNorm -------------------
__global__ void ln_kernel(const float* __restrict__ x, const float* __restrict__ g,
                          const float* __restrict__ b, float* __restrict__ out) {
    int row = blockIdx.x;
    const float* xr = x + (size_t)row * DIM;
    int t = threadIdx.x;
    float v[4];
    float s = 0.f, s2 = 0.f;
#pragma unroll
    for (int i = 0; i < 4; i++) {
        float u = xr[t + i * 256];
        v[i] = u; s += u; s2 += u * u;
    }
    __shared__ float red[17];
#pragma unroll
    for (int o = 16; o > 0; o >>= 1) {
        s  += __shfl_xor_sync(0xffffffffu, s,  o);
        s2 += __shfl_xor_sync(0xffffffffu, s2, o);
    }
    int w = t >> 5;
    if ((t & 31) == 0) { red[w] = s; red[w + 8] = s2; }
    __syncthreads();
    if (t < 32) {
        s  = (t < 8) ? red[t]     : 0.f;
        s2 = (t < 8) ? red[t + 8] : 0.f;
#pragma unroll
        for (int o = 4; o > 0; o >>= 1) {
            s  += __shfl_xor_sync(0xffffffffu, s,  o);
            s2 += __shfl_xor_sync(0xffffffffu, s2, o);
        }
        if (t == 0) {
            float mean = s * (1.0f / DIM);
            float var  = s2 * (1.0f / DIM) - mean * mean;
            red[0]  = mean;
            red[16] = rsqrtf(var + 1e-5f);
        }
    }
    __syncthreads();
    float mean = red[0], rstd = red[16];
    float* orow = out + (size_t)row * DIM;
#pragma unroll
    for (int i = 0; i < 4; i++) {
        int c = t + i * 256;
        orow[c] = (v[i] - mean) * rstd * g[c] + b[c];
    }
}

// ------------------- weight transpose + tf32 round: Wt[n][k] = rna(W[k][n]) ----
__global__ void transpose_rna(const float* __restrict__ W, float* __restrict__ Wt,
                              int K, int N) {
    __shared__ float t[32][33];
    int bx = blockIdx.x * 32, by = blockIdx.y * 32;
    int x = threadIdx.x, y = threadIdx.y;
#pragma unroll
    for (int i = 0; i < 32; i += 8)
        t[y + i][x] = W[(size_t)(by + y + i) * N + bx + x];
    __syncthreads();
#pragma unroll
    for (int i = 0; i < 32; i += 8)
        Wt[(size_t)(bx + y + i) * K + by + x] = rna_tf32(t[x][y + i]);
}

// ------------------- mma.sync tf32 GEMM: C[M,N] = A[M,K] * Bt[N,K]^T ---------
#define GM_BUF 16384
#define GM_SMEM (4 * GM_BUF + 1024)

template<int EPI>  // 0 plain, 2 bias+gelu, 3 bias+residual
__global__ __launch_bounds__(256)
void gemm_mma(const float* __restrict__ A, const float* __restrict__ Bt,
              const float* __restrict__ bias, const float* __restrict__ res,
              float* __restrict__ C, int K, int Ndim) {
    extern __shared__ char smraw[];
    uint32_t sbase = (smem_u32(smraw) + 1023u) & ~1023u;

    int tid = threadIdx.x;
    int wid = tid >> 5, lane = tid & 31;
    int wm = wid & 1, wn = wid >> 1;
    int brow = blockIdx.y << 7, bcol = blockIdx.x << 7;
    int g = lane >> 3, r = lane & 7;

    float acc[4][4][4];
#pragma unroll
    for (int i = 0; i < 4; i++)
#pragma unroll
        for (int j = 0; j < 4; j++)
#pragma unroll
            for (int q = 0; q < 4; q++) acc[i][j][q] = 0.f;

    const int KT = K >> 5;
    float4 aprefetch[4];

    {
        const float* Ab = A + (size_t)brow * K;
#pragma unroll
        for (int i = 0; i < 4; i++) {
            int idx = tid + i * 256;
            int rr = idx >> 3, ck = idx & 7;
            aprefetch[i] = *(const float4*)(Ab + (size_t)rr * K + (ck << 2));
        }
        const float* Bb = Bt + (size_t)bcol * K;
#pragma unroll
        for (int i = 0; i < 4; i++) {
            int idx = tid + i * 256;
            int rr = idx >> 3, ck = idx & 7;
            uint32_t dst = sbase + 2 * GM_BUF + sw128((uint32_t)(rr * 128 + (ck << 4)));
            cp_async16(dst, Bb + (size_t)rr * K + (ck << 2));
        }
        CP_COMMIT();
    }

    for (int kt = 0; kt < KT; kt++) {
        int b = kt & 1;
        uint32_t Ab_s = sbase + b * GM_BUF;
        uint32_t Bb_s = sbase + 2 * GM_BUF + b * GM_BUF;
#pragma unroll
        for (int i = 0; i < 4; i++) {
            int idx = tid + i * 256;
            int rr = idx >> 3, ck = idx & 7;
            float4 v = aprefetch[i];
            v.x = rna_tf32(v.x); v.y = rna_tf32(v.y);
            v.z = rna_tf32(v.z); v.w = rna_tf32(v.w);
            *(float4*)(smraw + (Ab_s - smem_u32(smraw)) + sw128((uint32_t)(rr * 128 + (ck << 4)))) = v;
        }
        if (kt + 1 < KT) {
            const float* Ab = A + (size_t)brow * K + ((kt + 1) << 5);
#pragma unroll
            for (int i = 0; i < 4; i++) {
                int idx = tid + i * 256;
                int rr = idx >> 3, ck = idx & 7;
                aprefetch[i] = *(const float4*)(Ab + (size_t)rr * K + (ck << 2));
            }
            const float* Bb = Bt + (size_t)bcol * K + ((kt + 1) << 5);
            uint32_t Bnext = sbase + 2 * GM_BUF + (b ^ 1) * GM_BUF;
#pragma unroll
            for (int i = 0; i < 4; i++) {
                int idx = tid + i * 256;
                int rr = idx >> 3, ck = idx & 7;
                cp_async16(Bnext + sw128((uint32_t)(rr * 128 + (ck << 4))),
                           Bb + (size_t)rr * K + (ck << 2));
            }
            CP_COMMIT();
            CP_WAIT(1);
        } else {
            CP_WAIT(0);
        }
        __syncthreads();

#pragma unroll
        for (int ks = 0; ks < 4; ks++) {
            uint32_t afr[4][4];
#pragma unroll
            for (int im = 0; im < 4; im++) {
                int rowa = wm * 64 + im * 16 + r + (g & 1) * 8;
                uint32_t ck = (uint32_t)(ks * 2 + (g >> 1));
                ldsm4(afr[im][0], afr[im][1], afr[im][2], afr[im][3],
                      Ab_s + sw128((uint32_t)(rowa * 128) + (ck << 4)));
            }
            uint32_t bfr[4][2];
#pragma unroll
            for (int ip = 0; ip < 2; ip++) {
                int rowb = wn * 32 + ip * 16 + (g >> 1) * 8 + r;
                uint32_t ck = (uint32_t)(ks * 2 + (g & 1));
                ldsm4(bfr[2 * ip][0], bfr[2 * ip][1], bfr[2 * ip + 1][0], bfr[2 * ip + 1][1],
                      Bb_s + sw128((uint32_t)(rowb * 128) + (ck << 4)));
            }
#pragma unroll
            for (int im = 0; im < 4; im++)
#pragma unroll
                for (int in = 0; in < 4; in++)
                    mma_tf32(acc[im][in], afr[im], bfr[in][0], bfr[in][1]);
        }
        if (kt + 1 < KT) __syncthreads();
    }

    int lr = lane >> 2, lc = (lane & 3) << 1;
#pragma unroll
    for (int im = 0; im < 4; im++) {
#pragma unroll
        for (int half = 0; half < 2; half++) {
            int row = brow + wm * 64 + im * 16 + lr + half * 8;
            float* Crow = C + (size_t)row * Ndim;
            const float* Rrow = (EPI == 3) ? (res + (size_t)row * Ndim) : nullptr;
#pragma unroll
            for (int in = 0; in < 4; in++) {
                int col = bcol + wn * 32 + in * 8 + lc;
                float u0 = acc[im][in][half * 2 + 0];
                float u1 = acc[im][in][half * 2 + 1];
                if (EPI >= 2) { u0 += bias[col]; u1 += bias[col + 1]; }
                if (EPI == 2) {
                    u0 = 0.5f * u0 * (1.0f + erff(u0 * 0.70710678118654752f));
                    u1 = 0.5f * u1 * (1.0f + erff(u1 * 0.70710678118654752f));
                }
                if (EPI == 3) { u0 += Rrow[col]; u1 += Rrow[col + 1]; }
                float2 v = make_float2(u0, u1);
                *(float2*)(Crow + col) = v;
            }
        }
    }
}

// ------------------- tensor-core flash attention -------------------
// CTA: one (b,h), 128 query rows. 8 warps x 16 rows. key tile = 64.
#define A_SQ  0                    // 2 planes x 128x128B = 32768
#define A_SK  32768                // 2 planes x 64x128B  = 16384
#define A_SVT 49152                // 2 planes x 64x128B  = 16384
#define A_SP  65536                // 2 planes x 128x128B = 32768
#define A_SMEM (98304 + 1024)

__global__ __launch_bounds__(256, 2)
void attn_mma(const float* __restrict__ qkv, float* __restrict__ o) {
    extern __shared__ char smraw[];
    uint32_t sraw = smem_u32(smraw);
    uint32_t sb = (sraw + 1023u) & ~1023u;
    char* smb = smraw + (sb - sraw);

    int tid = threadIdx.x;
    int w = tid >> 5, lane = tid & 31;
    int g = lane >> 3, r = lane & 7;
    int lr = lane >> 2, lc = lane & 3;

    int bh = blockIdx.y;
    int b = bh >> 4, h = bh & 15;
    int q0 = blockIdx.x << 7;
    const float* gq = qkv + (size_t)b * SEQ * 3 * DIM + h * HD;
    const float* gk = gq + DIM;
    const float* gv = gq + 2 * DIM;

    // ---- load Q tile 128x64 (rounded) ----
#pragma unroll
    for (int i = 0; i < 8; i++) {
        int idx = tid + i * 256;
        int row = idx >> 4, f4 = idx & 15;
        int pl = f4 >> 3, ck = f4 & 7;
        float4 v = *(const float4*)(gq + (size_t)(q0 + row) * (3 * DIM) + (f4 << 2));
        v.x = rna_tf32(v.x); v.y = rna_tf32(v.y);
        v.z = rna_tf32(v.z); v.w = rna_tf32(v.w);
        *(float4*)(smb + A_SQ + pl * 16384 + sw128((uint32_t)(row * 128 + (ck << 4)))) = v;
    }

    float m0 = -1e30f, m1 = -1e30f, l0 = 0.f, l1 = 0.f;
    float oacc[8][4];
#pragma unroll
    for (int j = 0; j < 8; j++)
#pragma unroll
        for (int q = 0; q < 4; q++) oacc[j][q] = 0.f;

    for (int kt = 0; kt < SEQ; kt += 64) {
        __syncthreads();   // prev PV done (and Q load on first iter)
        // ---- load K tile 64x64 (rounded) ----
#pragma unroll
        for (int i = 0; i < 4; i++) {
            int idx = tid + i * 256;
            int row = idx >> 4, f4 = idx & 15;
            int pl = f4 >> 3, ck = f4 & 7;
            float4 v = *(const float4*)(gk + (size_t)(kt + row) * (3 * DIM) + (f4 << 2));
            v.x = rna_tf32(v.x); v.y = rna_tf32(v.y);
            v.z = rna_tf32(v.z); v.w = rna_tf32(v.w);
            *(float4*)(smb + A_SK + pl * 8192 + sw128((uint32_t)(row * 128 + (ck << 4)))) = v;
        }
        // ---- load V tile, transposed into Vt[d][key] (rounded) ----
#pragma unroll
        for (int i = 0; i < 4; i++) {
            int idx = tid + i * 256;
            int key = idx & 63, d0 = (idx >> 6) << 2;
            float4 v = *(const float4*)(gv + (size_t)(kt + key) * (3 * DIM) + d0);
            char* base = smb + A_SVT + (key >> 5) * 8192;
            uint32_t cb = (uint32_t)((key & 31) << 2);
            *(float*)(base + sw128((uint32_t)((d0 + 0) * 128) + cb)) = rna_tf32(v.x);
            *(float*)(base + sw128((uint32_t)((d0 + 1) * 128) + cb)) = rna_tf32(v.y);
            *(float*)(base + sw128((uint32_t)((d0 + 2) * 128) + cb)) = rna_tf32(v.z);
            *(float*)(base + sw128((uint32_t)((d0 + 3) * 128) + cb)) = rna_tf32(v.w);
        }
        __syncthreads();

        // ---- S = Q K^T (warp: 16 q-rows x 64 keys) ----
        float sacc[8][4];
#pragma unroll
        for (int j = 0; j < 8; j++)
#pragma unroll
            for (int q = 0; q < 4; q++) sacc[j][q] = 0.f;

#pragma unroll
        for (int pk = 0; pk < 2; pk++) {
#pragma unroll
            for (int ks = 0; ks < 4; ks++) {
                uint32_t afr[4];
                int rowa = w * 16 + r + (g & 1) * 8;
                ldsm4(afr[0], afr[1], afr[2], afr[3],
                      sb + A_SQ + pk * 16384 +
                      sw128((uint32_t)(rowa * 128) + (uint32_t)((ks * 2 + (g >> 1)) << 4)));
                uint32_t bfr[8][2];
#pragma unroll
                for (int ip = 0; ip < 4; ip++) {
                    int rowb = ip * 16 + (g >> 1) * 8 + r;
                    ldsm4(bfr[2 * ip][0], bfr[2 * ip][1], bfr[2 * ip + 1][0], bfr[2 * ip + 1][1],
                          sb + A_SK + pk * 8192 +
                          sw128((uint32_t)(rowb * 128) + (uint32_t)((ks * 2 + (g & 1)) << 4)));
                }
#pragma unroll
                for (int j = 0; j < 8; j++)
                    mma_tf32(sacc[j], afr, bfr[j][0], bfr[j][1]);
            }
        }

        // ---- online softmax on fragments ----
        float rm0 = -1e30f, rm1 = -1e30f;
#pragma unroll
        for (int j = 0; j < 8; j++) {
            rm0 = fmaxf(rm0, fmaxf(sacc[j][0], sacc[j][1]));
            rm1 = fmaxf(rm1, fmaxf(sacc[j][2], sacc[j][3]));
        }
        rm0 *= ATT_SCALE; rm1 *= ATT_SCALE;
#pragma unroll
        for (int off = 1; off < 4; off <<= 1) {
            rm0 = fmaxf(rm0, __shfl_xor_sync(0xffffffffu, rm0, off));
            rm1 = fmaxf(rm1, __shfl_xor_sync(0xffffffffu, rm1, off));
        }
        float nm0 = fmaxf(m0, rm0), nm1 = fmaxf(m1, rm1);
        float corr0 = __expf(m0 - nm0), corr1 = __expf(m1 - nm1);
        m0 = nm0; m1 = nm1;
        float ls0 = 0.f, ls1 = 0.f;
        int prow0 = w * 16 + lr;
#pragma unroll
        for (int j = 0; j < 8; j++) {
            float p0 = rna_tf32(__expf(sacc[j][0] * ATT_SCALE - m0));
            float p1 = rna_tf32(__expf(sacc[j][1] * ATT_SCALE - m0));
            float p2 = rna_tf32(__expf(sacc[j][2] * ATT_SCALE - m1));
            float p3 = rna_tf32(__expf(sacc[j][3] * ATT_SCALE - m1));
            ls0 += p0 + p1; ls1 += p2 + p3;
            char* base = smb + A_SP + (j >> 2) * 16384;
            uint32_t cb = (uint32_t)(((j & 3) * 8 + 2 * lc) << 2);
            *(float2*)(base + sw128((uint32_t)(prow0 * 128) + cb)) = make_float2(p0, p1);
            *(float2*)(base + sw128((uint32_t)((prow0 + 8) * 128) + cb)) = make_float2(p2, p3);
        }
        // FIX (R4 bug): reduce row-sums across the 4-lane row group
#pragma unroll
        for (int off = 1; off < 4; off <<= 1) {
            ls0 += __shfl_xor_sync(0xffffffffu, ls0, off);
            ls1 += __shfl_xor_sync(0xffffffffu, ls1, off);
        }
        l0 = l0 * corr0 + ls0;
        l1 = l1 * corr1 + ls1;
#pragma unroll
        for (int j = 0; j < 8; j++) {
            oacc[j][0] *= corr0; oacc[j][1] *= corr0;
            oacc[j][2] *= corr1; oacc[j][3] *= corr1;
        }
        __syncwarp();

        // ---- O += P V  (A=P rows=q, k=keys; B=Vt rows=d, cols=keys) ----
#pragma unroll
        for (int pk = 0; pk < 2; pk++) {
#pragma unroll
            for (int ks = 0; ks < 4; ks++) {
                uint32_t afr[4];
                int rowa = w * 16 + r + (g & 1) * 8;
                ldsm4(afr[0], afr[1], afr[2], afr[3],
                      sb + A_SP + pk * 16384 +
                      sw128((uint32_t)(rowa * 128) + (uint32_t)((ks * 2 + (g >> 1)) << 4)));
                uint32_t bfr[8][2];
#pragma unroll
                for (int ip = 0; ip < 4; ip++) {
                    int rowb = ip * 16 + (g >> 1) * 8 + r;
                    ldsm4(bfr[2 * ip][0], bfr[2 * ip][1], bfr[2 * ip + 1][0], bfr[2 * ip + 1][1],
                          sb + A_SVT + pk * 8192 +
                          sw128((uint32_t)(rowb * 128) + (uint32_t)((ks * 2 + (g & 1)) << 4)));
                }
#pragma unroll
                for (int j = 0; j < 8; j++)
                    mma_tf32(oacc[j], afr, bfr[j][0], bfr[j][1]);
            }
        }
    }

    // ---- write O ----
    float inv0 = 1.0f / l0, inv1 = 1.0f / l1;
    int row0 = q0 + w * 16 + lr;
#pragma unroll
    for (int j = 0; j < 8; j++) {
        int col = h * HD + j * 8 + 2 * lc;
        *(float2*)(o + (size_t)(b * SEQ + row0) * DIM + col) =
            make_float2(oacc[j][0] * inv0, oacc[j][1] * inv0);
        *(float2*)(o + (size_t)(b * SEQ + row0 + 8) * DIM + col) =
            make_float2(oacc[j][2] * inv1, oacc[j][3] * inv1);
    }
}

// ------------------- host orchestration -------------------
extern "C" void kernel_launch(void* const* d_in, const int* in_sizes, int n_in,
                              void* d_out, int out_size) {
    const float* x     = (const float*)d_in[0];
    const float* ln1_g = (const float*)d_in[1];
    const float* ln1_b = (const float*)d_in[2];
    const float* w_qkv = (const float*)d_in[3];
    const float* w_out = (const float*)d_in[4];
    const float* b_out = (const float*)d_in[5];
    const float* ln2_g = (const float*)d_in[6];
    const float* ln2_b = (const float*)d_in[7];
    const float* w1    = (const float*)d_in[8];
    const float* b1    = (const float*)d_in[9];
    const float* w2    = (const float*)d_in[10];
    const float* b2    = (const float*)d_in[11];
    float* out = (float*)d_out;

    float *h, *qkvb, *ob, *mlpb, *wtq, *wto, *wt1, *wt2;
    cudaGetSymbolAddress((void**)&h,    g_h);
    cudaGetSymbolAddress((void**)&qkvb, g_qkv);
    cudaGetSymbolAddress((void**)&ob,   g_o);
    cudaGetSymbolAddress((void**)&mlpb, g_mlp);
    cudaGetSymbolAddress((void**)&wtq,  g_wt_qkv);
    cudaGetSymbolAddress((void**)&wto,  g_wt_out);
    cudaGetSymbolAddress((void**)&wt1,  g_wt1);
    cudaGetSymbolAddress((void**)&wt2,  g_wt2);

    cudaFuncSetAttribute(attn_mma, cudaFuncAttributeMaxDynamicSharedMemorySize, A_SMEM);
    cudaFuncSetAttribute(gemm_mma<0>, cudaFuncAttributeMaxDynamicSharedMemorySize, GM_SMEM);
    cudaFuncSetAttribute(gemm_mma<2>, cudaFuncAttributeMaxDynamicSharedMemorySize, GM_SMEM);
    cudaFuncSetAttribute(gemm_mma<3>, cudaFuncAttributeMaxDynamicSharedMemorySize, GM_SMEM);

    // pre-transpose + tf32-round all weights
    dim3 tb(32, 8);
    for (int l = 0; l < DEPTH; l++) {
        transpose_rna<<<dim3(3 * DIM / 32, DIM / 32), tb>>>(
            w_qkv + (size_t)l * DIM * 3 * DIM, wtq + (size_t)l * 3 * DIM * DIM, DIM, 3 * DIM);
        transpose_rna<<<dim3(DIM / 32, DIM / 32), tb>>>(
            w_out + (size_t)l * DIM * DIM, wto + (size_t)l * DIM * DIM, DIM, DIM);
        transpose_rna<<<dim3(MLPD / 32, DIM / 32), tb>>>(
            w1 + (size_t)l * DIM * MLPD, wt1 + (size_t)l * MLPD * DIM, DIM, MLPD);
        transpose_rna<<<dim3(DIM / 32, MLPD / 32), tb>>>(
            w2 + (size_t)l * MLPD * DIM, wt2 + (size_t)l * DIM * MLPD, MLPD, DIM);
    }

    cudaMemcpyAsync(out, x, (size_t)MROWS * DIM * sizeof(float),
                    cudaMemcpyDeviceToDevice);

    for (int lyr = 0; lyr < DEPTH; lyr++) {
        // --- attention block ---
        ln_kernel<<<MROWS, 256>>>(out, ln1_g + lyr * DIM, ln1_b + lyr * DIM, h);
        gemm_mma<0><<<dim3(3 * DIM / 128, MROWS / 128), 256, GM_SMEM>>>(
            h, wtq + (size_t)lyr * 3 * DIM * DIM, nullptr, nullptr,
            qkvb, DIM, 3 * DIM);
        attn_mma<<<dim3(SEQ / 128, BATCH * HEADS), 256, A_SMEM>>>(qkvb, ob);
        gemm_mma<3><<<dim3(DIM / 128, MROWS / 128), 256, GM_SMEM>>>(
            ob, wto + (size_t)lyr * DIM * DIM, b_out + lyr * DIM, out,
            out, DIM, DIM);
        // --- MLP block ---
        ln_kernel<<<MROWS, 256>>>(out, ln2_g + lyr * DIM, ln2_b + lyr * DIM, h);
        gemm_mma<2><<<dim3(MLPD / 128, MROWS / 128), 256, GM_SMEM>>>(
            h, wt1 + (size_t)lyr * MLPD * DIM, b1 + (size_t)lyr * MLPD, nullptr,
            mlpb, DIM, MLPD);
        gemm_mma<3><<<dim3(DIM / 128, MROWS / 128), 256, GM_SMEM>>>(
            mlpb, wt2 + (size_t)lyr * DIM * MLPD, b2 + lyr * DIM, out,
            out, MLPD, DIM);
    }
}

// round 6
// speedup vs baseline: 4.2001x; 1.1279x over previous
#include <cuda_runtime.h>
#include <math.h>
#include <stdint.h>

#define BATCH 4
#define SEQ   1024
#define DIM   1024
#define HEADS 16
#define HD    64
#define MLPD  4096
#define DEPTH 4
#define MROWS (BATCH*SEQ)          // 4096
#define ATT_SCALE (1.0f/32.0f)     // DIM^-0.5

// ------------------- scratch (no allocation allowed) -------------------
__device__ float g_h   [MROWS*DIM];
__device__ float g_qkv [MROWS*3*DIM];
__device__ float g_o   [MROWS*DIM];
__device__ float g_mlp [MROWS*MLPD];
// transposed (N-major) tf32-rounded weights
__device__ float g_wt_qkv[DEPTH*3*DIM*DIM];
__device__ float g_wt_out[DEPTH*DIM*DIM];
__device__ float g_wt1   [DEPTH*MLPD*DIM];
__device__ float g_wt2   [DEPTH*DIM*MLPD];

// ------------------- helpers -------------------
__device__ __forceinline__ uint32_t smem_u32(const void* p) {
    uint32_t a;
    asm("{ .reg .u64 t; cvta.to.shared.u64 t, %1; cvt.u32.u64 %0, t; }" : "=r"(a) : "l"(p));
    return a;
}
__device__ __forceinline__ float rna_tf32(float x) {
    float r; asm("cvt.rna.tf32.f32 %0, %1;" : "=f"(r) : "f"(x)); return r;
}
static __device__ __forceinline__ uint32_t sw128(uint32_t off) {
    return off ^ ((off >> 3) & 0x70);
}
__device__ __forceinline__ void ldsm4(uint32_t& d0, uint32_t& d1, uint32_t& d2,
                                      uint32_t& d3, uint32_t addr) {
    asm volatile("ldmatrix.sync.aligned.m8n8.x4.shared.b16 {%0,%1,%2,%3}, [%4];"
                 : "=r"(d0), "=r"(d1), "=r"(d2), "=r"(d3) : "r"(addr));
}
__device__ __forceinline__ void mma_tf32(float* c, const uint32_t* a,
                                         uint32_t b0, uint32_t b1) {
    asm volatile(
        "mma.sync.aligned.m16n8k8.row.col.f32.tf32.tf32.f32 "
        "{%0,%1,%2,%3}, {%4,%5,%6,%7}, {%8,%9}, {%0,%1,%2,%3};"
        : "+f"(c[0]), "+f"(c[1]), "+f"(c[2]), "+f"(c[3])
        : "r"(a[0]), "r"(a[1]), "r"(a[2]), "r"(a[3]), "r"(b0), "r"(b1));
}
__device__ __forceinline__ void cp_async16(uint32_t dst, const void* src) {
    asm volatile("cp.async.ca.shared.global [%0], [%1], 16;"
                 :: "r"(dst), "l"(src) : "memory");
}
#define CP_COMMIT() asm volatile("cp.async.commit_group;" ::: "memory")
#define CP_WAIT(n)  asm volatile("cp.async.wait_group %0;" :: "n"(n) : "memory")

// ------------------- LayerNorm (output rounded to tf32 for GEMM A) --------
__global__ void ln_kernel(const float* __restrict__ x, const float* __restrict__ g,
                          const float* __restrict__ b, float* __restrict__ out) {
    int row = blockIdx.x;
    const float* xr = x + (size_t)row * DIM;
    int t = threadIdx.x;
    float v[4];
    float s = 0.f, s2 = 0.f;
#pragma unroll
    for (int i = 0; i < 4; i++) {
        float u = xr[t + i * 256];
        v[i] = u; s += u; s2 += u * u;
    }
    __shared__ float red[17];
#pragma unroll
    for (int o = 16; o > 0; o >>= 1) {
        s  += __shfl_xor_sync(0xffffffffu, s,  o);
        s2 += __shfl_xor_sync(0xffffffffu, s2, o);
    }
    int w = t >> 5;
    if ((t & 31) == 0) { red[w] = s; red[w + 8] = s2; }
    __syncthreads();
    if (t < 32) {
        s  = (t < 8) ? red[t]     : 0.f;
        s2 = (t < 8) ? red[t + 8] : 0.f;
#pragma unroll
        for (int o = 4; o > 0; o >>= 1) {
            s  += __shfl_xor_sync(0xffffffffu, s,  o);
            s2 += __shfl_xor_sync(0xffffffffu, s2, o);
        }
        if (t == 0) {
            float mean = s * (1.0f / DIM);
            float var  = s2 * (1.0f / DIM) - mean * mean;
            red[0]  = mean;
            red[16] = rsqrtf(var + 1e-5f);
        }
    }
    __syncthreads();
    float mean = red[0], rstd = red[16];
    float* orow = out + (size_t)row * DIM;
#pragma unroll
    for (int i = 0; i < 4; i++) {
        int c = t + i * 256;
        orow[c] = rna_tf32((v[i] - mean) * rstd * g[c] + b[c]);
    }
}

// ------------------- weight transpose + tf32 round: Wt[n][k] = rna(W[k][n]) ----
__global__ void transpose_rna(const float* __restrict__ W, float* __restrict__ Wt,
                              int K, int N) {
    __shared__ float t[32][33];
    int bx = blockIdx.x * 32, by = blockIdx.y * 32;
    int x = threadIdx.x, y = threadIdx.y;
#pragma unroll
    for (int i = 0; i < 32; i += 8)
        t[y + i][x] = W[(size_t)(by + y + i) * N + bx + x];
    __syncthreads();
#pragma unroll
    for (int i = 0; i < 32; i += 8)
        Wt[(size_t)(bx + y + i) * K + by + x] = rna_tf32(t[x][y + i]);
}

// ------------------- mma.sync tf32 GEMM: C[M,N] = A[M,K] * Bt[N,K]^T ---------
// Both operands pre-rounded tf32 in GMEM. CTA tile 128x128, BK=32,
// double-buffered cp.async, 8 warps (2m x 4n), 2 CTAs/SM.
#define GM_BUF 16384
#define GM_SMEM (4 * GM_BUF + 1024)

template<int EPI>  // 0 plain, 2 bias+gelu(round), 3 bias+residual
__global__ __launch_bounds__(256, 2)
void gemm_mma(const float* __restrict__ A, const float* __restrict__ Bt,
              const float* __restrict__ bias, const float* __restrict__ res,
              float* __restrict__ C, int K, int Ndim) {
    extern __shared__ char smraw[];
    uint32_t sbase = (smem_u32(smraw) + 1023u) & ~1023u;

    int tid = threadIdx.x;
    int wid = tid >> 5, lane = tid & 31;
    int wm = wid & 1, wn = wid >> 1;
    int brow = blockIdx.y << 7, bcol = blockIdx.x << 7;
    int g = lane >> 3, r = lane & 7;

    float acc[4][4][4];
#pragma unroll
    for (int i = 0; i < 4; i++)
#pragma unroll
        for (int j = 0; j < 4; j++)
#pragma unroll
            for (int q = 0; q < 4; q++) acc[i][j][q] = 0.f;

    const int KT = K >> 5;
    int arow = tid >> 3, ack = tid & 7;   // each thread: 4 rows apart stride 32

    // issue one 128x32 tile (A or B) into smem buffer via cp.async
    auto issue_tile = [&](uint32_t dstbase, const float* src) {
#pragma unroll
        for (int i = 0; i < 4; i++) {
            int rr = arow + i * 32;
            cp_async16(dstbase + sw128((uint32_t)(rr * 128 + (ack << 4))),
                       src + (size_t)rr * K + (ack << 2));
        }
    };

    // prologue: stage 0
    issue_tile(sbase, A + (size_t)brow * K);
    issue_tile(sbase + 2 * GM_BUF, Bt + (size_t)bcol * K);
    CP_COMMIT();

    for (int kt = 0; kt < KT; kt++) {
        int b = kt & 1;
        uint32_t Ab_s = sbase + b * GM_BUF;
        uint32_t Bb_s = sbase + 2 * GM_BUF + b * GM_BUF;

        CP_WAIT(0);
        __syncthreads();

        if (kt + 1 < KT) {
            int nb = b ^ 1;
            issue_tile(sbase + nb * GM_BUF,
                       A + (size_t)brow * K + ((kt + 1) << 5));
            issue_tile(sbase + 2 * GM_BUF + nb * GM_BUF,
                       Bt + (size_t)bcol * K + ((kt + 1) << 5));
            CP_COMMIT();
        }

#pragma unroll
        for (int ks = 0; ks < 4; ks++) {
            uint32_t afr[4][4];
#pragma unroll
            for (int im = 0; im < 4; im++) {
                int rowa = wm * 64 + im * 16 + r + (g & 1) * 8;
                uint32_t ck = (uint32_t)(ks * 2 + (g >> 1));
                ldsm4(afr[im][0], afr[im][1], afr[im][2], afr[im][3],
                      Ab_s + sw128((uint32_t)(rowa * 128) + (ck << 4)));
            }
            uint32_t bfr[4][2];
#pragma unroll
            for (int ip = 0; ip < 2; ip++) {
                int rowb = wn * 32 + ip * 16 + (g >> 1) * 8 + r;
                uint32_t ck = (uint32_t)(ks * 2 + (g & 1));
                ldsm4(bfr[2 * ip][0], bfr[2 * ip][1], bfr[2 * ip + 1][0], bfr[2 * ip + 1][1],
                      Bb_s + sw128((uint32_t)(rowb * 128) + (ck << 4)));
            }
#pragma unroll
            for (int im = 0; im < 4; im++)
#pragma unroll
                for (int in = 0; in < 4; in++)
                    mma_tf32(acc[im][in], afr[im], bfr[in][0], bfr[in][1]);
        }
    }

    int lr = lane >> 2, lc = (lane & 3) << 1;
#pragma unroll
    for (int im = 0; im < 4; im++) {
#pragma unroll
        for (int half = 0; half < 2; half++) {
            int row = brow + wm * 64 + im * 16 + lr + half * 8;
            float* Crow = C + (size_t)row * Ndim;
            const float* Rrow = (EPI == 3) ? (res + (size_t)row * Ndim) : nullptr;
#pragma unroll
            for (int in = 0; in < 4; in++) {
                int col = bcol + wn * 32 + in * 8 + lc;
                float u0 = acc[im][in][half * 2 + 0];
                float u1 = acc[im][in][half * 2 + 1];
                if (EPI >= 2) { u0 += bias[col]; u1 += bias[col + 1]; }
                if (EPI == 2) {
                    u0 = rna_tf32(0.5f * u0 * (1.0f + erff(u0 * 0.70710678118654752f)));
                    u1 = rna_tf32(0.5f * u1 * (1.0f + erff(u1 * 0.70710678118654752f)));
                }
                if (EPI == 3) { u0 += Rrow[col]; u1 += Rrow[col + 1]; }
                float2 v = make_float2(u0, u1);
                *(float2*)(Crow + col) = v;
            }
        }
    }
}

// ------------------- tensor-core flash attention -------------------
// CTA: one (b,h), 128 query rows. 8 warps x 16 rows. key tile = 64.
#define A_SQ  0                    // 2 planes x 128x128B = 32768
#define A_SK  32768                // 2 planes x 64x128B  = 16384
#define A_SVT 49152                // 2 planes x 64x128B  = 16384
#define A_SP  65536                // 2 planes x 128x128B = 32768
#define A_SMEM (98304 + 1024)

__global__ __launch_bounds__(256, 2)
void attn_mma(const float* __restrict__ qkv, float* __restrict__ o) {
    extern __shared__ char smraw[];
    uint32_t sraw = smem_u32(smraw);
    uint32_t sb = (sraw + 1023u) & ~1023u;
    char* smb = smraw + (sb - sraw);

    int tid = threadIdx.x;
    int w = tid >> 5, lane = tid & 31;
    int g = lane >> 3, r = lane & 7;
    int lr = lane >> 2, lc = lane & 3;

    int bh = blockIdx.y;
    int b = bh >> 4, h = bh & 15;
    int q0 = blockIdx.x << 7;
    const float* gq = qkv + (size_t)b * SEQ * 3 * DIM + h * HD;
    const float* gk = gq + DIM;
    const float* gv = gq + 2 * DIM;

    // ---- load Q tile 128x64 (rounded) ----
#pragma unroll
    for (int i = 0; i < 8; i++) {
        int idx = tid + i * 256;
        int row = idx >> 4, f4 = idx & 15;
        int pl = f4 >> 3, ck = f4 & 7;
        float4 v = *(const float4*)(gq + (size_t)(q0 + row) * (3 * DIM) + (f4 << 2));
        v.x = rna_tf32(v.x); v.y = rna_tf32(v.y);
        v.z = rna_tf32(v.z); v.w = rna_tf32(v.w);
        *(float4*)(smb + A_SQ + pl * 16384 + sw128((uint32_t)(row * 128 + (ck << 4)))) = v;
    }

    float m0 = -1e30f, m1 = -1e30f, l0 = 0.f, l1 = 0.f;
    float oacc[8][4];
#pragma unroll
    for (int j = 0; j < 8; j++)
#pragma unroll
        for (int q = 0; q < 4; q++) oacc[j][q] = 0.f;

    for (int kt = 0; kt < SEQ; kt += 64) {
        __syncthreads();
        // ---- load K tile 64x64 (rounded) ----
#pragma unroll
        for (int i = 0; i < 4; i++) {
            int idx = tid + i * 256;
            int row = idx >> 4, f4 = idx & 15;
            int pl = f4 >> 3, ck = f4 & 7;
            float4 v = *(const float4*)(gk + (size_t)(kt + row) * (3 * DIM) + (f4 << 2));
            v.x = rna_tf32(v.x); v.y = rna_tf32(v.y);
            v.z = rna_tf32(v.z); v.w = rna_tf32(v.w);
            *(float4*)(smb + A_SK + pl * 8192 + sw128((uint32_t)(row * 128 + (ck << 4)))) = v;
        }
        // ---- load V tile, transposed into Vt[d][key] (rounded) ----
#pragma unroll
        for (int i = 0; i < 4; i++) {
            int idx = tid + i * 256;
            int key = idx & 63, d0 = (idx >> 6) << 2;
            float4 v = *(const float4*)(gv + (size_t)(kt + key) * (3 * DIM) + d0);
            char* base = smb + A_SVT + (key >> 5) * 8192;
            uint32_t cb = (uint32_t)((key & 31) << 2);
            *(float*)(base + sw128((uint32_t)((d0 + 0) * 128) + cb)) = rna_tf32(v.x);
            *(float*)(base + sw128((uint32_t)((d0 + 1) * 128) + cb)) = rna_tf32(v.y);
            *(float*)(base + sw128((uint32_t)((d0 + 2) * 128) + cb)) = rna_tf32(v.z);
            *(float*)(base + sw128((uint32_t)((d0 + 3) * 128) + cb)) = rna_tf32(v.w);
        }
        __syncthreads();

        // ---- S = Q K^T ----
        float sacc[8][4];
#pragma unroll
        for (int j = 0; j < 8; j++)
#pragma unroll
            for (int q = 0; q < 4; q++) sacc[j][q] = 0.f;

#pragma unroll
        for (int pk = 0; pk < 2; pk++) {
#pragma unroll
            for (int ks = 0; ks < 4; ks++) {
                uint32_t afr[4];
                int rowa = w * 16 + r + (g & 1) * 8;
                ldsm4(afr[0], afr[1], afr[2], afr[3],
                      sb + A_SQ + pk * 16384 +
                      sw128((uint32_t)(rowa * 128) + (uint32_t)((ks * 2 + (g >> 1)) << 4)));
                uint32_t bfr[8][2];
#pragma unroll
                for (int ip = 0; ip < 4; ip++) {
                    int rowb = ip * 16 + (g >> 1) * 8 + r;
                    ldsm4(bfr[2 * ip][0], bfr[2 * ip][1], bfr[2 * ip + 1][0], bfr[2 * ip + 1][1],
                          sb + A_SK + pk * 8192 +
                          sw128((uint32_t)(rowb * 128) + (uint32_t)((ks * 2 + (g & 1)) << 4)));
                }
#pragma unroll
                for (int j = 0; j < 8; j++)
                    mma_tf32(sacc[j], afr, bfr[j][0], bfr[j][1]);
            }
        }

        // ---- online softmax ----
        float rm0 = -1e30f, rm1 = -1e30f;
#pragma unroll
        for (int j = 0; j < 8; j++) {
            rm0 = fmaxf(rm0, fmaxf(sacc[j][0], sacc[j][1]));
            rm1 = fmaxf(rm1, fmaxf(sacc[j][2], sacc[j][3]));
        }
        rm0 *= ATT_SCALE; rm1 *= ATT_SCALE;
#pragma unroll
        for (int off = 1; off < 4; off <<= 1) {
            rm0 = fmaxf(rm0, __shfl_xor_sync(0xffffffffu, rm0, off));
            rm1 = fmaxf(rm1, __shfl_xor_sync(0xffffffffu, rm1, off));
        }
        float nm0 = fmaxf(m0, rm0), nm1 = fmaxf(m1, rm1);
        float corr0 = __expf(m0 - nm0), corr1 = __expf(m1 - nm1);
        m0 = nm0; m1 = nm1;
        float ls0 = 0.f, ls1 = 0.f;
        int prow0 = w * 16 + lr;
#pragma unroll
        for (int j = 0; j < 8; j++) {
            float p0 = rna_tf32(__expf(sacc[j][0] * ATT_SCALE - m0));
            float p1 = rna_tf32(__expf(sacc[j][1] * ATT_SCALE - m0));
            float p2 = rna_tf32(__expf(sacc[j][2] * ATT_SCALE - m1));
            float p3 = rna_tf32(__expf(sacc[j][3] * ATT_SCALE - m1));
            ls0 += p0 + p1; ls1 += p2 + p3;
            char* base = smb + A_SP + (j >> 2) * 16384;
            uint32_t cb = (uint32_t)(((j & 3) * 8 + 2 * lc) << 2);
            *(float2*)(base + sw128((uint32_t)(prow0 * 128) + cb)) = make_float2(p0, p1);
            *(float2*)(base + sw128((uint32_t)((prow0 + 8) * 128) + cb)) = make_float2(p2, p3);
        }
#pragma unroll
        for (int off = 1; off < 4; off <<= 1) {
            ls0 += __shfl_xor_sync(0xffffffffu, ls0, off);
            ls1 += __shfl_xor_sync(0xffffffffu, ls1, off);
        }
        l0 = l0 * corr0 + ls0;
        l1 = l1 * corr1 + ls1;
#pragma unroll
        for (int j = 0; j < 8; j++) {
            oacc[j][0] *= corr0; oacc[j][1] *= corr0;
            oacc[j][2] *= corr1; oacc[j][3] *= corr1;
        }
        __syncwarp();

        // ---- O += P V ----
#pragma unroll
        for (int pk = 0; pk < 2; pk++) {
#pragma unroll
            for (int ks = 0; ks < 4; ks++) {
                uint32_t afr[4];
                int rowa = w * 16 + r + (g & 1) * 8;
                ldsm4(afr[0], afr[1], afr[2], afr[3],
                      sb + A_SP + pk * 16384 +
                      sw128((uint32_t)(rowa * 128) + (uint32_t)((ks * 2 + (g >> 1)) << 4)));
                uint32_t bfr[8][2];
#pragma unroll
                for (int ip = 0; ip < 4; ip++) {
                    int rowb = ip * 16 + (g >> 1) * 8 + r;
                    ldsm4(bfr[2 * ip][0], bfr[2 * ip][1], bfr[2 * ip + 1][0], bfr[2 * ip + 1][1],
                          sb + A_SVT + pk * 8192 +
                          sw128((uint32_t)(rowb * 128) + (uint32_t)((ks * 2 + (g & 1)) << 4)));
                }
#pragma unroll
                for (int j = 0; j < 8; j++)
                    mma_tf32(oacc[j], afr, bfr[j][0], bfr[j][1]);
            }
        }
    }

    // ---- write O (rounded: consumed as GEMM A by proj) ----
    float inv0 = 1.0f / l0, inv1 = 1.0f / l1;
    int row0 = q0 + w * 16 + lr;
#pragma unroll
    for (int j = 0; j < 8; j++) {
        int col = h * HD + j * 8 + 2 * lc;
        *(float2*)(o + (size_t)(b * SEQ + row0) * DIM + col) =
            make_float2(rna_tf32(oacc[j][0] * inv0), rna_tf32(oacc[j][1] * inv0));
        *(float2*)(o + (size_t)(b * SEQ + row0 + 8) * DIM + col) =
            make_float2(rna_tf32(oacc[j][2] * inv1), rna_tf32(oacc[j][3] * inv1));
    }
}

// ------------------- host orchestration -------------------
extern "C" void kernel_launch(void* const* d_in, const int* in_sizes, int n_in,
                              void* d_out, int out_size) {
    const float* x     = (const float*)d_in[0];
    const float* ln1_g = (const float*)d_in[1];
    const float* ln1_b = (const float*)d_in[2];
    const float* w_qkv = (const float*)d_in[3];
    const float* w_out = (const float*)d_in[4];
    const float* b_out = (const float*)d_in[5];
    const float* ln2_g = (const float*)d_in[6];
    const float* ln2_b = (const float*)d_in[7];
    const float* w1    = (const float*)d_in[8];
    const float* b1    = (const float*)d_in[9];
    const float* w2    = (const float*)d_in[10];
    const float* b2    = (const float*)d_in[11];
    float* out = (float*)d_out;

    float *h, *qkvb, *ob, *mlpb, *wtq, *wto, *wt1, *wt2;
    cudaGetSymbolAddress((void**)&h,    g_h);
    cudaGetSymbolAddress((void**)&qkvb, g_qkv);
    cudaGetSymbolAddress((void**)&ob,   g_o);
    cudaGetSymbolAddress((void**)&mlpb, g_mlp);
    cudaGetSymbolAddress((void**)&wtq,  g_wt_qkv);
    cudaGetSymbolAddress((void**)&wto,  g_wt_out);
    cudaGetSymbolAddress((void**)&wt1,  g_wt1);
    cudaGetSymbolAddress((void**)&wt2,  g_wt2);

    cudaFuncSetAttribute(attn_mma, cudaFuncAttributeMaxDynamicSharedMemorySize, A_SMEM);
    cudaFuncSetAttribute(gemm_mma<0>, cudaFuncAttributeMaxDynamicSharedMemorySize, GM_SMEM);
    cudaFuncSetAttribute(gemm_mma<2>, cudaFuncAttributeMaxDynamicSharedMemorySize, GM_SMEM);
    cudaFuncSetAttribute(gemm_mma<3>, cudaFuncAttributeMaxDynamicSharedMemorySize, GM_SMEM);

    // pre-transpose + tf32-round all weights
    dim3 tb(32, 8);
    for (int l = 0; l < DEPTH; l++) {
        transpose_rna<<<dim3(3 * DIM / 32, DIM / 32), tb>>>(
            w_qkv + (size_t)l * DIM * 3 * DIM, wtq + (size_t)l * 3 * DIM * DIM, DIM, 3 * DIM);
        transpose_rna<<<dim3(DIM / 32, DIM / 32), tb>>>(
            w_out + (size_t)l * DIM * DIM, wto + (size_t)l * DIM * DIM, DIM, DIM);
        transpose_rna<<<dim3(MLPD / 32, DIM / 32), tb>>>(
            w1 + (size_t)l * DIM * MLPD, wt1 + (size_t)l * MLPD * DIM, DIM, MLPD);
        transpose_rna<<<dim3(DIM / 32, MLPD / 32), tb>>>(
            w2 + (size_t)l * MLPD * DIM, wt2 + (size_t)l * DIM * MLPD, MLPD, DIM);
    }

    cudaMemcpyAsync(out, x, (size_t)MROWS * DIM * sizeof(float),
                    cudaMemcpyDeviceToDevice);

    for (int lyr = 0; lyr < DEPTH; lyr++) {
        // --- attention block ---
        ln_kernel<<<MROWS, 256>>>(out, ln1_g + lyr * DIM, ln1_b + lyr * DIM, h);
        gemm_mma<0><<<dim3(3 * DIM / 128, MROWS / 128), 256, GM_SMEM>>>(
            h, wtq + (size_t)lyr * 3 * DIM * DIM, nullptr, nullptr,
            qkvb, DIM, 3 * DIM);
        attn_mma<<<dim3(SEQ / 128, BATCH * HEADS), 256, A_SMEM>>>(qkvb, ob);
        gemm_mma<3><<<dim3(DIM / 128, MROWS / 128), 256, GM_SMEM>>>(
            ob, wto + (size_t)lyr * DIM * DIM, b_out + lyr * DIM, out,
            out, DIM, DIM);
        // --- MLP block ---
        ln_kernel<<<MROWS, 256>>>(out, ln2_g + lyr * DIM, ln2_b + lyr * DIM, h);
        gemm_mma<2><<<dim3(MLPD / 128, MROWS / 128), 256, GM_SMEM>>>(
            h, wt1 + (size_t)lyr * MLPD * DIM, b1 + (size_t)lyr * MLPD, nullptr,
            mlpb, DIM, MLPD);
        gemm_mma<3><<<dim3(DIM / 128, MROWS / 128), 256, GM_SMEM>>>(
            mlpb, wt2 + (size_t)lyr * DIM * MLPD, b2 + lyr * DIM, out,
            out, MLPD, DIM);
    }
}

// round 7
// speedup vs baseline: 7.7110x; 1.8359x over previous
#include <cuda_runtime.h>
#include <cuda_fp16.h>
#include <math.h>
#include <stdint.h>

#define BATCH 4
#define SEQ   1024
#define DIM   1024
#define HEADS 16
#define HD    64
#define MLPD  4096
#define DEPTH 4
#define MROWS (BATCH*SEQ)          // 4096
#define ATT_SCALE (1.0f/32.0f)     // DIM^-0.5

// ------------------- scratch (no allocation allowed) -------------------
__device__ __half g_h   [MROWS*DIM];
__device__ __half g_qkv [MROWS*3*DIM];
__device__ __half g_o   [MROWS*DIM];
__device__ __half g_mlp [MROWS*MLPD];
// transposed (N-major) fp16 weights
__device__ __half g_wt_qkv[DEPTH*3*DIM*DIM];
__device__ __half g_wt_out[DEPTH*DIM*DIM];
__device__ __half g_wt1   [DEPTH*MLPD*DIM];
__device__ __half g_wt2   [DEPTH*DIM*MLPD];

// ------------------- helpers -------------------
__device__ __forceinline__ uint32_t smem_u32(const void* p) {
    uint32_t a;
    asm("{ .reg .u64 t; cvta.to.shared.u64 t, %1; cvt.u32.u64 %0, t; }" : "=r"(a) : "l"(p));
    return a;
}
static __device__ __forceinline__ uint32_t sw128(uint32_t off) {
    return off ^ ((off >> 3) & 0x70);
}
__device__ __forceinline__ void ldsm4(uint32_t& d0, uint32_t& d1, uint32_t& d2,
                                      uint32_t& d3, uint32_t addr) {
    asm volatile("ldmatrix.sync.aligned.m8n8.x4.shared.b16 {%0,%1,%2,%3}, [%4];"
                 : "=r"(d0), "=r"(d1), "=r"(d2), "=r"(d3) : "r"(addr));
}
__device__ __forceinline__ void ldsm4t(uint32_t& d0, uint32_t& d1, uint32_t& d2,
                                       uint32_t& d3, uint32_t addr) {
    asm volatile("ldmatrix.sync.aligned.m8n8.x4.trans.shared.b16 {%0,%1,%2,%3}, [%4];"
                 : "=r"(d0), "=r"(d1), "=r"(d2), "=r"(d3) : "r"(addr));
}
__device__ __forceinline__ void mma_f16(float* c, const uint32_t* a,
                                        uint32_t b0, uint32_t b1) {
    asm volatile(
        "mma.sync.aligned.m16n8k16.row.col.f32.f16.f16.f32 "
        "{%0,%1,%2,%3}, {%4,%5,%6,%7}, {%8,%9}, {%0,%1,%2,%3};"
        : "+f"(c[0]), "+f"(c[1]), "+f"(c[2]), "+f"(c[3])
        : "r"(a[0]), "r"(a[1]), "r"(a[2]), "r"(a[3]), "r"(b0), "r"(b1));
}
__device__ __forceinline__ void cp_async16(uint32_t dst, const void* src) {
    asm volatile("cp.async.ca.shared.global [%0], [%1], 16;"
                 :: "r"(dst), "l"(src) : "memory");
}
#define CP_COMMIT() asm volatile("cp.async.commit_group;" ::: "memory")
#define CP_WAIT(n)  asm volatile("cp.async.wait_group %0;" :: "n"(n) : "memory")

// ------------------- LayerNorm (fp32 in, fp16 out) --------
__global__ void ln_kernel(const float* __restrict__ x, const float* __restrict__ g,
                          const float* __restrict__ b, __half* __restrict__ out) {
    int row = blockIdx.x;
    const float* xr = x + (size_t)row * DIM;
    int t = threadIdx.x;
    float v[4];
    float s = 0.f, s2 = 0.f;
#pragma unroll
    for (int i = 0; i < 4; i++) {
        float u = xr[t + i * 256];
        v[i] = u; s += u; s2 += u * u;
    }
    __shared__ float red[17];
#pragma unroll
    for (int o = 16; o > 0; o >>= 1) {
        s  += __shfl_xor_sync(0xffffffffu, s,  o);
        s2 += __shfl_xor_sync(0xffffffffu, s2, o);
    }
    int w = t >> 5;
    if ((t & 31) == 0) { red[w] = s; red[w + 8] = s2; }
    __syncthreads();
    if (t < 32) {
        s  = (t < 8) ? red[t]     : 0.f;
        s2 = (t < 8) ? red[t + 8] : 0.f;
#pragma unroll
        for (int o = 4; o > 0; o >>= 1) {
            s  += __shfl_xor_sync(0xffffffffu, s,  o);
            s2 += __shfl_xor_sync(0xffffffffu, s2, o);
        }
        if (t == 0) {
            float mean = s * (1.0f / DIM);
            float var  = s2 * (1.0f / DIM) - mean * mean;
            red[0]  = mean;
            red[16] = rsqrtf(var + 1e-5f);
        }
    }
    __syncthreads();
    float mean = red[0], rstd = red[16];
    __half* orow = out + (size_t)row * DIM;
#pragma unroll
    for (int i = 0; i < 4; i++) {
        int c = t + i * 256;
        orow[c] = __float2half_rn((v[i] - mean) * rstd * g[c] + b[c]);
    }
}

// ------------------- weight transpose to fp16: Wt[n][k] = h(W[k][n]) ----
__global__ void transpose_h(const float* __restrict__ W, __half* __restrict__ Wt,
                            int K, int N) {
    __shared__ float t[32][33];
    int bx = blockIdx.x * 32, by = blockIdx.y * 32;
    int x = threadIdx.x, y = threadIdx.y;
#pragma unroll
    for (int i = 0; i < 32; i += 8)
        t[y + i][x] = W[(size_t)(by + y + i) * N + bx + x];
    __syncthreads();
#pragma unroll
    for (int i = 0; i < 32; i += 8)
        Wt[(size_t)(bx + y + i) * K + by + x] = __float2half_rn(t[x][y + i]);
}

// ------------------- fp16 mma GEMM: C[M,N] = A[M,K] * Bt[N,K]^T ---------
// CTA tile 128x128, BK=64 (one 128B half-row), double-buffered cp.async,
// 8 warps (2m x 4n), 2 CTAs/SM.
#define GM_BUF 16384
#define GM_SMEM (4 * GM_BUF + 1024)

template<int EPI>  // 0 plain->half, 2 bias+gelu->half, 3 bias+residual->float
__global__ __launch_bounds__(256, 2)
void gemm_mma(const __half* __restrict__ A, const __half* __restrict__ Bt,
              const float* __restrict__ bias, const float* __restrict__ res,
              void* __restrict__ Cv, int K, int Ndim) {
    extern __shared__ char smraw[];
    uint32_t sbase = (smem_u32(smraw) + 1023u) & ~1023u;

    int tid = threadIdx.x;
    int wid = tid >> 5, lane = tid & 31;
    int wm = wid & 1, wn = wid >> 1;
    int brow = blockIdx.y << 7, bcol = blockIdx.x << 7;
    int g = lane >> 3, r = lane & 7;

    float acc[4][4][4];
#pragma unroll
    for (int i = 0; i < 4; i++)
#pragma unroll
        for (int j = 0; j < 4; j++)
#pragma unroll
            for (int q = 0; q < 4; q++) acc[i][j][q] = 0.f;

    const int KT = K >> 6;             // 64 halves per K-tile
    int arow = tid >> 3, ack = tid & 7;

    auto issue_tile = [&](uint32_t dstbase, const __half* src) {
#pragma unroll
        for (int i = 0; i < 4; i++) {
            int rr = arow + i * 32;
            cp_async16(dstbase + sw128((uint32_t)(rr * 128 + (ack << 4))),
                       src + (size_t)rr * K + (ack << 3));
        }
    };

    issue_tile(sbase, A + (size_t)brow * K);
    issue_tile(sbase + 2 * GM_BUF, Bt + (size_t)bcol * K);
    CP_COMMIT();

    for (int kt = 0; kt < KT; kt++) {
        int b = kt & 1;
        uint32_t Ab_s = sbase + b * GM_BUF;
        uint32_t Bb_s = sbase + 2 * GM_BUF + b * GM_BUF;

        CP_WAIT(0);
        __syncthreads();

        if (kt + 1 < KT) {
            int nb = b ^ 1;
            issue_tile(sbase + nb * GM_BUF,
                       A + (size_t)brow * K + ((kt + 1) << 6));
            issue_tile(sbase + 2 * GM_BUF + nb * GM_BUF,
                       Bt + (size_t)bcol * K + ((kt + 1) << 6));
            CP_COMMIT();
        }

#pragma unroll
        for (int ks = 0; ks < 4; ks++) {   // k16 per step; chunks (2ks, 2ks+1)
            uint32_t afr[4][4];
#pragma unroll
            for (int im = 0; im < 4; im++) {
                int rowa = wm * 64 + im * 16 + r + (g & 1) * 8;
                uint32_t ck = (uint32_t)(ks * 2 + (g >> 1));
                ldsm4(afr[im][0], afr[im][1], afr[im][2], afr[im][3],
                      Ab_s + sw128((uint32_t)(rowa * 128) + (ck << 4)));
            }
            uint32_t bfr[4][2];
#pragma unroll
            for (int ip = 0; ip < 2; ip++) {
                int rowb = wn * 32 + ip * 16 + (g >> 1) * 8 + r;
                uint32_t ck = (uint32_t)(ks * 2 + (g & 1));
                ldsm4(bfr[2 * ip][0], bfr[2 * ip][1], bfr[2 * ip + 1][0], bfr[2 * ip + 1][1],
                      Bb_s + sw128((uint32_t)(rowb * 128) + (ck << 4)));
            }
#pragma unroll
            for (int im = 0; im < 4; im++)
#pragma unroll
                for (int in = 0; in < 4; in++)
                    mma_f16(acc[im][in], afr[im], bfr[in][0], bfr[in][1]);
        }
    }

    int lr = lane >> 2, lc = (lane & 3) << 1;
#pragma unroll
    for (int im = 0; im < 4; im++) {
#pragma unroll
        for (int half_ = 0; half_ < 2; half_++) {
            int row = brow + wm * 64 + im * 16 + lr + half_ * 8;
            const float* Rrow = (EPI == 3) ? (res + (size_t)row * Ndim) : nullptr;
#pragma unroll
            for (int in = 0; in < 4; in++) {
                int col = bcol + wn * 32 + in * 8 + lc;
                float u0 = acc[im][in][half_ * 2 + 0];
                float u1 = acc[im][in][half_ * 2 + 1];
                if (EPI >= 2) { u0 += bias[col]; u1 += bias[col + 1]; }
                if (EPI == 2) {
                    u0 = 0.5f * u0 * (1.0f + erff(u0 * 0.70710678118654752f));
                    u1 = 0.5f * u1 * (1.0f + erff(u1 * 0.70710678118654752f));
                }
                if (EPI == 3) {
                    float* Crow = (float*)Cv + (size_t)row * Ndim;
                    *(float2*)(Crow + col) = make_float2(u0 + Rrow[col], u1 + Rrow[col + 1]);
                } else {
                    __half* Crow = (__half*)Cv + (size_t)row * Ndim;
                    *(__half2*)(Crow + col) = __floats2half2_rn(u0, u1);
                }
            }
        }
    }
}

// ------------------- fp16 tensor-core flash attention -------------------
// CTA: one (b,h), 128 query rows. 8 warps x 16 rows. key tile = 64.
// planes (128B rows, sw128): Q 128r, K 64r, V 64r, P 128r
#define A_SQ  0                    // 16384
#define A_SK  16384                // 8192
#define A_SV  24576                // 8192
#define A_SP  32768                // 16384
#define A_SMEM (49152 + 1024)

__global__ __launch_bounds__(256, 2)
void attn_mma(const __half* __restrict__ qkv, __half* __restrict__ o) {
    extern __shared__ char smraw[];
    uint32_t sraw = smem_u32(smraw);
    uint32_t sb = (sraw + 1023u) & ~1023u;
    char* smb = smraw + (sb - sraw);

    int tid = threadIdx.x;
    int w = tid >> 5, lane = tid & 31;
    int g = lane >> 3, r = lane & 7;
    int lr = lane >> 2, lc = lane & 3;

    int bh = blockIdx.y;
    int b = bh >> 4, h = bh & 15;
    int q0 = blockIdx.x << 7;
    const __half* gq = qkv + (size_t)b * SEQ * 3 * DIM + h * HD;
    const __half* gk = gq + DIM;
    const __half* gv = gq + 2 * DIM;

    // ---- Q tile 128x64h via cp.async ----
#pragma unroll
    for (int i = 0; i < 4; i++) {
        int idx = tid + i * 256;
        int row = idx >> 3, ck = idx & 7;
        cp_async16(sb + A_SQ + sw128((uint32_t)(row * 128 + (ck << 4))),
                   gq + (size_t)(q0 + row) * (3 * DIM) + (ck << 3));
    }
    CP_COMMIT();

    float m0 = -1e30f, m1 = -1e30f, l0 = 0.f, l1 = 0.f;
    float oacc[8][4];
#pragma unroll
    for (int j = 0; j < 8; j++)
#pragma unroll
        for (int q = 0; q < 4; q++) oacc[j][q] = 0.f;

    for (int kt = 0; kt < SEQ; kt += 64) {
        __syncthreads();   // prev PV reads of K/V planes done
        // ---- K,V tiles 64x64h via cp.async ----
#pragma unroll
        for (int i = 0; i < 2; i++) {
            int idx = tid + i * 256;
            int row = idx >> 3, ck = idx & 7;
            cp_async16(sb + A_SK + sw128((uint32_t)(row * 128 + (ck << 4))),
                       gk + (size_t)(kt + row) * (3 * DIM) + (ck << 3));
            cp_async16(sb + A_SV + sw128((uint32_t)(row * 128 + (ck << 4))),
                       gv + (size_t)(kt + row) * (3 * DIM) + (ck << 3));
        }
        CP_COMMIT();
        CP_WAIT(0);
        __syncthreads();

        // ---- S = Q K^T  (d = k-dim, 4 k16 steps) ----
        float sacc[8][4];
#pragma unroll
        for (int j = 0; j < 8; j++)
#pragma unroll
            for (int q = 0; q < 4; q++) sacc[j][q] = 0.f;

#pragma unroll
        for (int ks = 0; ks < 4; ks++) {
            uint32_t afr[4];
            int rowa = w * 16 + r + (g & 1) * 8;
            ldsm4(afr[0], afr[1], afr[2], afr[3],
                  sb + A_SQ + sw128((uint32_t)(rowa * 128) +
                                    (uint32_t)((ks * 2 + (g >> 1)) << 4)));
            uint32_t bfr[8][2];
#pragma unroll
            for (int ip = 0; ip < 4; ip++) {
                int rowb = ip * 16 + (g >> 1) * 8 + r;
                ldsm4(bfr[2 * ip][0], bfr[2 * ip][1], bfr[2 * ip + 1][0], bfr[2 * ip + 1][1],
                      sb + A_SK + sw128((uint32_t)(rowb * 128) +
                                        (uint32_t)((ks * 2 + (g & 1)) << 4)));
            }
#pragma unroll
            for (int j = 0; j < 8; j++)
                mma_f16(sacc[j], afr, bfr[j][0], bfr[j][1]);
        }

        // ---- online softmax ----
        float rm0 = -1e30f, rm1 = -1e30f;
#pragma unroll
        for (int j = 0; j < 8; j++) {
            rm0 = fmaxf(rm0, fmaxf(sacc[j][0], sacc[j][1]));
            rm1 = fmaxf(rm1, fmaxf(sacc[j][2], sacc[j][3]));
        }
        rm0 *= ATT_SCALE; rm1 *= ATT_SCALE;
#pragma unroll
        for (int off = 1; off < 4; off <<= 1) {
            rm0 = fmaxf(rm0, __shfl_xor_sync(0xffffffffu, rm0, off));
            rm1 = fmaxf(rm1, __shfl_xor_sync(0xffffffffu, rm1, off));
        }
        float nm0 = fmaxf(m0, rm0), nm1 = fmaxf(m1, rm1);
        float corr0 = __expf(m0 - nm0), corr1 = __expf(m1 - nm1);
        m0 = nm0; m1 = nm1;
        float ls0 = 0.f, ls1 = 0.f;
        int prow0 = w * 16 + lr;
#pragma unroll
        for (int j = 0; j < 8; j++) {
            __half2 hp0 = __floats2half2_rn(__expf(sacc[j][0] * ATT_SCALE - m0),
                                            __expf(sacc[j][1] * ATT_SCALE - m0));
            __half2 hp1 = __floats2half2_rn(__expf(sacc[j][2] * ATT_SCALE - m1),
                                            __expf(sacc[j][3] * ATT_SCALE - m1));
            float2 f0 = __half22float2(hp0), f1 = __half22float2(hp1);
            ls0 += f0.x + f0.y; ls1 += f1.x + f1.y;
            uint32_t cb = (uint32_t)((j * 8 + 2 * lc) << 1);   // halves*2 bytes
            *(__half2*)(smb + A_SP + sw128((uint32_t)(prow0 * 128) + cb)) = hp0;
            *(__half2*)(smb + A_SP + sw128((uint32_t)((prow0 + 8) * 128) + cb)) = hp1;
        }
#pragma unroll
        for (int off = 1; off < 4; off <<= 1) {
            ls0 += __shfl_xor_sync(0xffffffffu, ls0, off);
            ls1 += __shfl_xor_sync(0xffffffffu, ls1, off);
        }
        l0 = l0 * corr0 + ls0;
        l1 = l1 * corr1 + ls1;
#pragma unroll
        for (int j = 0; j < 8; j++) {
            oacc[j][0] *= corr0; oacc[j][1] *= corr0;
            oacc[j][2] *= corr1; oacc[j][3] *= corr1;
        }
        __syncwarp();

        // ---- O += P V  (keys = k-dim, 4 k16 steps; V via ldmatrix.trans) ----
#pragma unroll
        for (int ks = 0; ks < 4; ks++) {
            uint32_t afr[4];
            int rowa = w * 16 + r + (g & 1) * 8;
            ldsm4(afr[0], afr[1], afr[2], afr[3],
                  sb + A_SP + sw128((uint32_t)(rowa * 128) +
                                    (uint32_t)((ks * 2 + (g >> 1)) << 4)));
            uint32_t bfr[8][2];
#pragma unroll
            for (int idb = 0; idb < 4; idb++) {
                int rowv = ks * 16 + (g & 1) * 8 + r;
                uint32_t ck = (uint32_t)(idb * 2 + (g >> 1));
                ldsm4t(bfr[2 * idb][0], bfr[2 * idb][1], bfr[2 * idb + 1][0], bfr[2 * idb + 1][1],
                       sb + A_SV + sw128((uint32_t)(rowv * 128) + (ck << 4)));
            }
#pragma unroll
            for (int j = 0; j < 8; j++)
                mma_f16(oacc[j], afr, bfr[j][0], bfr[j][1]);
        }
    }

    // ---- write O (fp16, consumed as GEMM A) ----
    float inv0 = 1.0f / l0, inv1 = 1.0f / l1;
    int row0 = q0 + w * 16 + lr;
#pragma unroll
    for (int j = 0; j < 8; j++) {
        int col = h * HD + j * 8 + 2 * lc;
        *(__half2*)(o + (size_t)(b * SEQ + row0) * DIM + col) =
            __floats2half2_rn(oacc[j][0] * inv0, oacc[j][1] * inv0);
        *(__half2*)(o + (size_t)(b * SEQ + row0 + 8) * DIM + col) =
            __floats2half2_rn(oacc[j][2] * inv1, oacc[j][3] * inv1);
    }
}

// ------------------- host orchestration -------------------
extern "C" void kernel_launch(void* const* d_in, const int* in_sizes, int n_in,
                              void* d_out, int out_size) {
    const float* x     = (const float*)d_in[0];
    const float* ln1_g = (const float*)d_in[1];
    const float* ln1_b = (const float*)d_in[2];
    const float* w_qkv = (const float*)d_in[3];
    const float* w_out = (const float*)d_in[4];
    const float* b_out = (const float*)d_in[5];
    const float* ln2_g = (const float*)d_in[6];
    const float* ln2_b = (const float*)d_in[7];
    const float* w1    = (const float*)d_in[8];
    const float* b1    = (const float*)d_in[9];
    const float* w2    = (const float*)d_in[10];
    const float* b2    = (const float*)d_in[11];
    float* out = (float*)d_out;

    __half *h, *qkvb, *ob, *mlpb, *wtq, *wto, *wt1, *wt2;
    cudaGetSymbolAddress((void**)&h,    g_h);
    cudaGetSymbolAddress((void**)&qkvb, g_qkv);
    cudaGetSymbolAddress((void**)&ob,   g_o);
    cudaGetSymbolAddress((void**)&mlpb, g_mlp);
    cudaGetSymbolAddress((void**)&wtq,  g_wt_qkv);
    cudaGetSymbolAddress((void**)&wto,  g_wt_out);
    cudaGetSymbolAddress((void**)&wt1,  g_wt1);
    cudaGetSymbolAddress((void**)&wt2,  g_wt2);

    cudaFuncSetAttribute(attn_mma, cudaFuncAttributeMaxDynamicSharedMemorySize, A_SMEM);
    cudaFuncSetAttribute(gemm_mma<0>, cudaFuncAttributeMaxDynamicSharedMemorySize, GM_SMEM);
    cudaFuncSetAttribute(gemm_mma<2>, cudaFuncAttributeMaxDynamicSharedMemorySize, GM_SMEM);
    cudaFuncSetAttribute(gemm_mma<3>, cudaFuncAttributeMaxDynamicSharedMemorySize, GM_SMEM);

    // pre-transpose + fp16-convert all weights
    dim3 tb(32, 8);
    for (int l = 0; l < DEPTH; l++) {
        transpose_h<<<dim3(3 * DIM / 32, DIM / 32), tb>>>(
            w_qkv + (size_t)l * DIM * 3 * DIM, wtq + (size_t)l * 3 * DIM * DIM, DIM, 3 * DIM);
        transpose_h<<<dim3(DIM / 32, DIM / 32), tb>>>(
            w_out + (size_t)l * DIM * DIM, wto + (size_t)l * DIM * DIM, DIM, DIM);
        transpose_h<<<dim3(MLPD / 32, DIM / 32), tb>>>(
            w1 + (size_t)l * DIM * MLPD, wt1 + (size_t)l * MLPD * DIM, DIM, MLPD);
        transpose_h<<<dim3(DIM / 32, MLPD / 32), tb>>>(
            w2 + (size_t)l * MLPD * DIM, wt2 + (size_t)l * DIM * MLPD, MLPD, DIM);
    }

    cudaMemcpyAsync(out, x, (size_t)MROWS * DIM * sizeof(float),
                    cudaMemcpyDeviceToDevice);

    for (int lyr = 0; lyr < DEPTH; lyr++) {
        // --- attention block ---
        ln_kernel<<<MROWS, 256>>>(out, ln1_g + lyr * DIM, ln1_b + lyr * DIM, h);
        gemm_mma<0><<<dim3(3 * DIM / 128, MROWS / 128), 256, GM_SMEM>>>(
            h, wtq + (size_t)lyr * 3 * DIM * DIM, nullptr, nullptr,
            qkvb, DIM, 3 * DIM);
        attn_mma<<<dim3(SEQ / 128, BATCH * HEADS), 256, A_SMEM>>>(qkvb, ob);
        gemm_mma<3><<<dim3(DIM / 128, MROWS / 128), 256, GM_SMEM>>>(
            ob, wto + (size_t)lyr * DIM * DIM, b_out + lyr * DIM, out,
            out, DIM, DIM);
        // --- MLP block ---
        ln_kernel<<<MROWS, 256>>>(out, ln2_g + lyr * DIM, ln2_b + lyr * DIM, h);
        gemm_mma<2><<<dim3(MLPD / 128, MROWS / 128), 256, GM_SMEM>>>(
            h, wt1 + (size_t)lyr * MLPD * DIM, b1 + (size_t)lyr * MLPD, nullptr,
            mlpb, DIM, MLPD);
        gemm_mma<3><<<dim3(DIM / 128, MROWS / 128), 256, GM_SMEM>>>(
            mlpb, wt2 + (size_t)lyr * DIM * MLPD, b2 + lyr * DIM, out,
            out, MLPD, DIM);
    }
}